// round 11
// baseline (speedup 1.0000x reference)
#include <cuda_runtime.h>
#include <cstdint>

#define B_  4
#define L_  2048
#define H_  256
#define NH_ 8
#define DH_ 32
#define M_  (B_*L_)   // 8192 rows

// ---------------------------------------------------------------------------
// Global scratch (allocation-free rule: __device__ globals)
// K(eff) split bf16 words, layout [b][h][tile32][key64][20 words] (16 used)
// V^T   split bf16 words, layout [b][h][tile32][drow32][36 words] (32 used)
// ---------------------------------------------------------------------------
__device__ __align__(16) uint32_t g_kh[B_*NH_*32*64*20];
__device__ __align__(16) uint32_t g_kl[B_*NH_*32*64*20];
__device__ __align__(16) uint32_t g_vh[B_*NH_*32*32*36];
__device__ __align__(16) uint32_t g_vl[B_*NH_*32*32*36];
__device__ __align__(16) float    g_hidden[M_ * H_];
__device__ int g_mflag[B_];   // 1 = no masked keys in this batch row

// ---------------------------------------------------------------------------
// helpers
// ---------------------------------------------------------------------------
__device__ __forceinline__ float ex2f(float x) {
    float r; asm("ex2.approx.f32 %0, %1;" : "=f"(r) : "f"(x)); return r;
}
__device__ __forceinline__ void mma16(float c[4], const uint32_t a[4],
                                      uint32_t b0, uint32_t b1) {
    asm("mma.sync.aligned.m16n8k16.row.col.f32.bf16.bf16.f32 "
        "{%0,%1,%2,%3},{%4,%5,%6,%7},{%8,%9},{%0,%1,%2,%3};"
        : "+f"(c[0]), "+f"(c[1]), "+f"(c[2]), "+f"(c[3])
        : "r"(a[0]), "r"(a[1]), "r"(a[2]), "r"(a[3]), "r"(b0), "r"(b1));
}
// pack (lo=x, hi=y) into bf16x2; split2 also returns residual word
__device__ __forceinline__ uint32_t packbf(float x, float y) {
    uint32_t r; asm("cvt.rn.bf16x2.f32 %0, %1, %2;" : "=r"(r) : "f"(y), "f"(x));
    return r;
}
__device__ __forceinline__ void split2(float x, float y,
                                       uint32_t& hw, uint32_t& lw) {
    hw = packbf(x, y);
    float xh = __uint_as_float(hw << 16);
    float yh = __uint_as_float(hw & 0xffff0000u);
    lw = packbf(x - xh, y - yh);
}
__device__ __forceinline__ void cp16(uint32_t saddr, const void* gaddr) {
    asm volatile("cp.async.cg.shared.global [%0], [%1], 16;"
                 :: "r"(saddr), "l"(gaddr));
}
__device__ __forceinline__ void cp_commit() {
    asm volatile("cp.async.commit_group;");
}
__device__ __forceinline__ void cp_wait0() {
    asm volatile("cp.async.wait_group 0;" ::: "memory");
}
__device__ __forceinline__ void cp_wait1() {
    asm volatile("cp.async.wait_group 1;" ::: "memory");
}

// word-position permutations: u = w&7, s = w>>3
// K rows have 16 words: pos = (u&3)*4 + 2s + (u>>2)
// V rows have 32 words: pos = (u&3)*8 + 2s + (u>>2)
__device__ __forceinline__ int kpos(int w) {
    return ((w & 3) << 2) + ((w >> 3) << 1) + ((w >> 2) & 1);
}
__device__ __forceinline__ int vpos(int w) {
    return ((w & 3) << 3) + ((w >> 3) << 1) + ((w >> 2) & 1);
}

// ---------------------------------------------------------------------------
// mask flag: g_mflag[b] = 1 iff mask[b][*] all nonzero
// ---------------------------------------------------------------------------
__global__ __launch_bounds__(128)
void maskflag(const int* __restrict__ mask)
{
    __shared__ int s[128];
    const int b = blockIdx.x, tid = threadIdx.x;
    int all1 = 1;
    for (int i = tid; i < L_; i += 128) all1 &= (mask[b * L_ + i] != 0);
    s[tid] = all1;
    __syncthreads();
    for (int st = 64; st; st >>= 1) {
        if (tid < st) s[tid] &= s[tid + st];
        __syncthreads();
    }
    if (tid == 0) g_mflag[b] = s[0];
}

// ---------------------------------------------------------------------------
// V prep: v [b][kv][h*32+d] f32  ->  g_vh/g_vl transposed split words
// ---------------------------------------------------------------------------
__global__ __launch_bounds__(128)
void vprep(const float* __restrict__ v)
{
    __shared__ float sv[64 * 36];
    __shared__ uint32_t swh[32 * 36], swl[32 * 36];
    const int bx = blockIdx.x;
    const int kt = bx & 31, h = (bx >> 5) & 7, b = bx >> 8;
    const int tid = threadIdx.x;
    const float* src = v + ((size_t)(b * L_ + kt * 64)) * H_ + h * 32;

    #pragma unroll
    for (int u = 0; u < 4; u++) {
        int idx = tid + u * 128;
        int row = idx >> 3, c4 = idx & 7;
        *(float4*)&sv[row * 36 + c4 * 4] = *(const float4*)&src[row * H_ + c4 * 4];
    }
    __syncthreads();
    #pragma unroll
    for (int u = 0; u < 8; u++) {
        int idx = tid + u * 128;
        int drow = idx >> 5, w = idx & 31;
        float x = sv[(2 * w) * 36 + drow];
        float y = sv[(2 * w + 1) * 36 + drow];
        uint32_t hw, lw; split2(x, y, hw, lw);
        int p = vpos(w);
        swh[drow * 36 + p] = hw;
        swl[drow * 36 + p] = lw;
    }
    __syncthreads();
    uint32_t* gh = g_vh + (size_t)bx * 1152;
    uint32_t* gl = g_vl + (size_t)bx * 1152;
    #pragma unroll
    for (int u = 0; u < 9; u++) {
        int idx = tid + u * 128;
        if (idx < 1152) { gh[idx] = swh[idx]; gl[idx] = swl[idx]; }
    }
}

// ---------------------------------------------------------------------------
// GEMM (bf16 3x, m16n8k16): out[m,n] = A·W^T + bias (+add). BM=128,BN=64,BK=32.
// ---------------------------------------------------------------------------
#define GAH 0
#define GAL (128 * 20)
#define GWH (2 * 128 * 20)
#define GWL (2 * 128 * 20 + 64 * 20)
#define GEMM_SMEM_WORDS (2 * 128 * 20 + 2 * 64 * 20)
#define GEMM_SMEM_BYTES (GEMM_SMEM_WORDS * 4)

template<bool KEFF>
__global__ __launch_bounds__(256)
void gemm_tc(const float* __restrict__ Ain,
             const float* __restrict__ W,
             const float* __restrict__ bias,
             const float* __restrict__ add,
             float* __restrict__ outp)
{
    extern __shared__ uint32_t smw[];
    const float* A = KEFF ? Ain : g_hidden;

    const int m0  = blockIdx.y * 128;
    const int n0  = blockIdx.x * 64;
    const int tid = threadIdx.x;
    const int warp   = tid >> 5;
    const int lane   = tid & 31;
    const int warp_m = warp >> 1;
    const int warp_n = warp & 1;
    const int g = lane >> 2;
    const int t = lane & 3;

    float acc[2][4][4] = {};

    float4 xa[4], xw[2];
    #pragma unroll
    for (int u = 0; u < 4; u++) {
        int idx = tid + u * 256;
        xa[u] = *(const float4*)&A[(size_t)(m0 + (idx >> 3)) * H_ + (idx & 7) * 4];
    }
    #pragma unroll
    for (int u = 0; u < 2; u++) {
        int idx = tid + u * 256;
        xw[u] = *(const float4*)&W[(size_t)(n0 + (idx >> 3)) * H_ + (idx & 7) * 4];
    }

    for (int k0 = 0; k0 < H_; k0 += 32) {
        #pragma unroll
        for (int u = 0; u < 4; u++) {
            int idx = tid + u * 256;
            int row = idx >> 3, c4 = idx & 7;
            uint32_t h0, l0, h1, l1;
            split2(xa[u].x, xa[u].y, h0, l0);
            split2(xa[u].z, xa[u].w, h1, l1);
            *(uint2*)&smw[GAH + row * 20 + c4 * 2] = make_uint2(h0, h1);
            *(uint2*)&smw[GAL + row * 20 + c4 * 2] = make_uint2(l0, l1);
        }
        #pragma unroll
        for (int u = 0; u < 2; u++) {
            int idx = tid + u * 256;
            int row = idx >> 3, c4 = idx & 7;
            uint32_t h0, l0, h1, l1;
            split2(xw[u].x, xw[u].y, h0, l0);
            split2(xw[u].z, xw[u].w, h1, l1);
            *(uint2*)&smw[GWH + row * 20 + c4 * 2] = make_uint2(h0, h1);
            *(uint2*)&smw[GWL + row * 20 + c4 * 2] = make_uint2(l0, l1);
        }
        __syncthreads();

        if (k0 + 32 < H_) {
            #pragma unroll
            for (int u = 0; u < 4; u++) {
                int idx = tid + u * 256;
                xa[u] = *(const float4*)&A[(size_t)(m0 + (idx >> 3)) * H_ +
                                           k0 + 32 + (idx & 7) * 4];
            }
            #pragma unroll
            for (int u = 0; u < 2; u++) {
                int idx = tid + u * 256;
                xw[u] = *(const float4*)&W[(size_t)(n0 + (idx >> 3)) * H_ +
                                           k0 + 32 + (idx & 7) * 4];
            }
        }

        #pragma unroll
        for (int s = 0; s < 2; s++) {
            uint32_t ah[2][4], al[2][4];
            #pragma unroll
            for (int mt = 0; mt < 2; mt++) {
                int r0 = (warp_m * 32 + mt * 16 + g) * 20 + 8 * s + t;
                ah[mt][0] = smw[GAH + r0];
                ah[mt][1] = smw[GAH + r0 + 160];      // +8 rows
                ah[mt][2] = smw[GAH + r0 + 4];
                ah[mt][3] = smw[GAH + r0 + 164];
                al[mt][0] = smw[GAL + r0];
                al[mt][1] = smw[GAL + r0 + 160];
                al[mt][2] = smw[GAL + r0 + 4];
                al[mt][3] = smw[GAL + r0 + 164];
            }
            #pragma unroll
            for (int nt = 0; nt < 4; nt++) {
                int rw = (warp_n * 32 + nt * 8 + g) * 20 + 8 * s + t;
                uint32_t wh0 = smw[GWH + rw];
                uint32_t wh1 = smw[GWH + rw + 4];
                uint32_t wl0 = smw[GWL + rw];
                uint32_t wl1 = smw[GWL + rw + 4];
                #pragma unroll
                for (int mt = 0; mt < 2; mt++) {
                    mma16(acc[mt][nt], al[mt], wh0, wh1);
                    mma16(acc[mt][nt], ah[mt], wl0, wl1);
                    mma16(acc[mt][nt], ah[mt], wh0, wh1);
                }
            }
        }
        __syncthreads();
    }

    #pragma unroll
    for (int mt = 0; mt < 2; mt++) {
        #pragma unroll
        for (int nt = 0; nt < 4; nt++) {
            int n  = n0 + warp_n * 32 + nt * 8 + 2 * t;
            int mA = m0 + warp_m * 32 + mt * 16 + g;
            int mB = mA + 8;
            float2 bs = *(const float2*)&bias[n];
            float x0 = acc[mt][nt][0] + bs.x, x1 = acc[mt][nt][1] + bs.y;
            float y0 = acc[mt][nt][2] + bs.x, y1 = acc[mt][nt][3] + bs.y;
            if (KEFF) {
                float2 a0 = *(const float2*)&add[(size_t)mA * H_ + n];
                float2 a1 = *(const float2*)&add[(size_t)mB * H_ + n];
                x0 += a0.x; x1 += a0.y; y0 += a1.x; y1 += a1.y;
                int h = n >> 5;
                int wd = (n & 31) >> 1;
                int p = kpos(wd);
                uint32_t hw, lw;
                {
                    int bi = mA >> 11, l = mA & 2047;
                    size_t base = (((size_t)(bi * NH_ + h) * 32 + (l >> 6)) * 64
                                   + (l & 63)) * 20 + p;
                    split2(x0, x1, hw, lw);
                    g_kh[base] = hw; g_kl[base] = lw;
                }
                {
                    int bi = mB >> 11, l = mB & 2047;
                    size_t base = (((size_t)(bi * NH_ + h) * 32 + (l >> 6)) * 64
                                   + (l & 63)) * 20 + p;
                    split2(y0, y1, hw, lw);
                    g_kh[base] = hw; g_kl[base] = lw;
                }
            } else {
                *(float2*)&outp[(size_t)mA * H_ + n] = make_float2(x0, x1);
                *(float2*)&outp[(size_t)mB * H_ + n] = make_float2(y0, y1);
            }
        }
    }
}

// ---------------------------------------------------------------------------
// Flash attention, bf16x3 m16n8k16, static softmax (exp2 domain), and
// CROSS-TILE SOFTWARE PIPELINING: S(kt+1) and PV(kt) are independent and
// emitted in one straight-line region -> 8 parallel mma chains. K/V smem is
// TRIPLE buffered (fill kt+2 || S reads kt+1 || PV reads kt).
// BQ=128 (8 warps, 256 threads), 2 CTAs/SM.
// ---------------------------------------------------------------------------
#define OKH 0
#define OKL 1280
#define OVH 2560
#define OVL 3712
#define OMS 4864
#define BUFSZ 4928
#define ATTN_SMEM_WORDS (3 * BUFSZ)
#define ATTN_SMEM_BYTES (ATTN_SMEM_WORDS * 4)

__device__ __forceinline__ void fill_tile(uint32_t sbase, uint32_t bufbase,
                                          int bh, int kt,
                                          const int* __restrict__ maskb)
{
    const int tid = threadIdx.x;
    size_t kb = ((size_t)bh * 32 + kt) * 1280;
    size_t vb = ((size_t)bh * 32 + kt) * 1152;
    const uint32_t* gkh = g_kh + kb;
    const uint32_t* gkl = g_kl + kb;
    const uint32_t* gvh = g_vh + vb;
    const uint32_t* gvl = g_vl + vb;
    #pragma unroll
    for (int u = 0; u < 2; u++) {
        int i = tid + u * 256;
        if (i < 320) {
            cp16(sbase + (bufbase + OKH + i * 4) * 4, gkh + i * 4);
            cp16(sbase + (bufbase + OKL + i * 4) * 4, gkl + i * 4);
        }
    }
    #pragma unroll
    for (int u = 0; u < 2; u++) {
        int i = tid + u * 256;
        if (i < 288) {
            cp16(sbase + (bufbase + OVH + i * 4) * 4, gvh + i * 4);
            cp16(sbase + (bufbase + OVL + i * 4) * 4, gvl + i * 4);
        }
    }
    if (tid < 16)
        cp16(sbase + (bufbase + OMS + tid * 4) * 4, maskb + kt * 64 + tid * 4);
    cp_commit();
}

// S = Q·Keff^T for a full 64-key tile (48 mma, 8 independent chains)
__device__ __forceinline__ void emit_S(float c[8][4],
                                       const uint32_t* __restrict__ base,
                                       const uint32_t qh[2][4],
                                       const uint32_t ql[2][4], int koff)
{
    const uint32_t* KH = base + OKH;
    const uint32_t* KL = base + OKL;
    #pragma unroll
    for (int j = 0; j < 8; j++) {
        #pragma unroll
        for (int x = 0; x < 4; x++) c[j][x] = 0.f;
        uint4 bhw = *(const uint4*)(KH + j * 160 + koff);
        uint4 blw = *(const uint4*)(KL + j * 160 + koff);
        mma16(c[j], qh[0], bhw.x, bhw.y);
        mma16(c[j], qh[1], bhw.z, bhw.w);
        mma16(c[j], ql[0], bhw.x, bhw.y);
        mma16(c[j], ql[1], bhw.z, bhw.w);
        mma16(c[j], qh[0], blw.x, blw.y);
        mma16(c[j], qh[1], blw.z, blw.w);
    }
}

// O += P·V for a full 64-key tile (48 mma, 4 independent chains)
__device__ __forceinline__ void emit_PV(float o[4][4],
                                        const uint32_t APH[4][4],
                                        const uint32_t APL[4][4],
                                        const uint32_t* __restrict__ base,
                                        int voff)
{
    const uint32_t* VH = base + OVH;
    const uint32_t* VL = base + OVL;
    #pragma unroll
    for (int nb = 0; nb < 4; nb++) {
        uint4 vh0 = *(const uint4*)(VH + nb * 288 + voff);
        uint4 vh1 = *(const uint4*)(VH + nb * 288 + voff + 4);
        uint4 vl0 = *(const uint4*)(VL + nb * 288 + voff);
        uint4 vl1 = *(const uint4*)(VL + nb * 288 + voff + 4);
        mma16(o[nb], APH[0], vh0.x, vh0.y);
        mma16(o[nb], APH[1], vh0.z, vh0.w);
        mma16(o[nb], APH[2], vh1.x, vh1.y);
        mma16(o[nb], APH[3], vh1.z, vh1.w);
        mma16(o[nb], APL[0], vh0.x, vh0.y);
        mma16(o[nb], APL[1], vh0.z, vh0.w);
        mma16(o[nb], APL[2], vh1.x, vh1.y);
        mma16(o[nb], APL[3], vh1.z, vh1.w);
        mma16(o[nb], APH[0], vl0.x, vl0.y);
        mma16(o[nb], APH[1], vl0.z, vl0.w);
        mma16(o[nb], APH[2], vl1.x, vl1.y);
        mma16(o[nb], APH[3], vl1.z, vl1.w);
    }
}

__global__ __launch_bounds__(256, 2)
void attn_tc(const float* __restrict__ q,
             const int*   __restrict__ mask,
             const float* __restrict__ scale_w)
{
    extern __shared__ uint32_t smu[];
    const uint32_t sbase = (uint32_t)__cvta_generic_to_shared(smu);

    const int b   = blockIdx.z;
    const int h   = blockIdx.y;
    const int q0  = blockIdx.x * 128;
    const int bh  = b * NH_ + h;
    const int tid = threadIdx.x;
    const int warp = tid >> 5;
    const int lane = tid & 31;
    const int g = lane >> 2;
    const int t = lane & 3;
    // exp2-domain: fold log2e into the Q pre-scale; p = exp2(s' - EOFF2)
    const float rs = 0.17677669529663687f * 1.4426950408889634f;
    const float EOFF2 = 23.083120654223414f;   // 16 * log2e

    const int r0l = warp * 16 + g;
    const int r1l = r0l + 8;
    const int* maskb = mask + b * L_;
    const int noMask = g_mflag[b];

    // ---- Q fragments: 2 k16-steps, split bf16 ----
    const float s0 = scale_w[h * L_ + q0 + r0l] * rs;
    const float s1 = scale_w[h * L_ + q0 + r1l] * rs;
    const float* qb = q + (size_t)(b * L_ + q0) * H_ + h * DH_;

    uint32_t qh[2][4], ql[2][4];
    #pragma unroll
    for (int s = 0; s < 2; s++) {
        float2 v0 = *(const float2*)&qb[r0l * H_ + s * 16 + 2 * t];
        float2 v2 = *(const float2*)&qb[r0l * H_ + s * 16 + 2 * t + 8];
        float2 v1 = *(const float2*)&qb[r1l * H_ + s * 16 + 2 * t];
        float2 v3 = *(const float2*)&qb[r1l * H_ + s * 16 + 2 * t + 8];
        split2(v0.x * s0, v0.y * s0, qh[s][0], ql[s][0]);
        split2(v1.x * s1, v1.y * s1, qh[s][1], ql[s][1]);
        split2(v2.x * s0, v2.y * s0, qh[s][2], ql[s][2]);
        split2(v3.x * s1, v3.y * s1, qh[s][3], ql[s][3]);
    }

    float l0 = 0.f, l1 = 0.f;
    float o[4][4] = {};
    float c[8][4];

    const int koff = g * 20 + t * 4;
    const int voff = g * 36 + t * 8;

    // rotating triple-buffer word offsets: cur (PV kt), nxt (S kt+1), fut (fill kt+2)
    uint32_t obc = 0, obn = BUFSZ, obf = 2 * BUFSZ;

    fill_tile(sbase, obc, bh, 0, maskb);   // group for tile 0
    fill_tile(sbase, obn, bh, 1, maskb);   // group for tile 1

    cp_wait1();            // tile 0 resident (tile 1 may still be in flight)
    __syncthreads();
    emit_S(c, smu + obc, qh, ql, koff);    // S(0)

    for (int kt = 0; kt < 32; kt++) {
        // ---- exp2/pack: c = S(kt) -> AP (frees c) ----
        if (!noMask) {
            const int* MS = (const int*)(smu + obc + OMS);
            #pragma unroll
            for (int j = 0; j < 8; j++) {
                int2 mv = *(const int2*)(MS + j * 8 + 2 * t);
                if (mv.x == 0) { c[j][0] = -1e9f; c[j][2] = -1e9f; }
                if (mv.y == 0) { c[j][1] = -1e9f; c[j][3] = -1e9f; }
            }
        }
        uint32_t APH[4][4], APL[4][4];
        #pragma unroll
        for (int kb = 0; kb < 4; kb++) {
            float pA0 = ex2f(c[2*kb][0]   - EOFF2);
            float pA1 = ex2f(c[2*kb][1]   - EOFF2);
            float pA2 = ex2f(c[2*kb][2]   - EOFF2);
            float pA3 = ex2f(c[2*kb][3]   - EOFF2);
            float pB0 = ex2f(c[2*kb+1][0] - EOFF2);
            float pB1 = ex2f(c[2*kb+1][1] - EOFF2);
            float pB2 = ex2f(c[2*kb+1][2] - EOFF2);
            float pB3 = ex2f(c[2*kb+1][3] - EOFF2);
            l0 += pA0 + pA1 + pB0 + pB1;
            l1 += pA2 + pA3 + pB2 + pB3;
            split2(pA0, pA1, APH[kb][0], APL[kb][0]);
            split2(pA2, pA3, APH[kb][1], APL[kb][1]);
            split2(pB0, pB1, APH[kb][2], APL[kb][2]);
            split2(pB2, pB3, APH[kb][3], APL[kb][3]);
        }

        if (kt < 31) {
            // tile kt+1 must be resident before S(kt+1)
            cp_wait0();
            __syncthreads();   // also: all warps done with PV(kt-1) reads of obf
            if (kt < 30)
                fill_tile(sbase, obf, bh, kt + 2, maskb);

            // ---- independent streams: S(kt+1) + PV(kt); ptxas interleaves ----
            emit_S(c, smu + obn, qh, ql, koff);
            emit_PV(o, APH, APL, smu + obc, voff);
        } else {
            emit_PV(o, APH, APL, smu + obc, voff);
        }

        // rotate buffers
        uint32_t tmp = obc; obc = obn; obn = obf; obf = tmp;
    }

    // ---- one-time l reduction across the 4-lane groups ----
    l0 += __shfl_xor_sync(0xffffffffu, l0, 1);
    l0 += __shfl_xor_sync(0xffffffffu, l0, 2);
    l1 += __shfl_xor_sync(0xffffffffu, l1, 1);
    l1 += __shfl_xor_sync(0xffffffffu, l1, 2);

    // ---- normalize + store (fused head transpose) ----
    float inv0 = 1.f / l0, inv1 = 1.f / l1;
    #pragma unroll
    for (int nb = 0; nb < 4; nb++) {
        int col = h * DH_ + nb * 8 + 2 * t;
        float2 w0 = make_float2(o[nb][0] * inv0, o[nb][1] * inv0);
        float2 w1 = make_float2(o[nb][2] * inv1, o[nb][3] * inv1);
        *(float2*)&g_hidden[(size_t)(b * L_ + q0 + r0l) * H_ + col] = w0;
        *(float2*)&g_hidden[(size_t)(b * L_ + q0 + r1l) * H_ + col] = w1;
    }
}

// ---------------------------------------------------------------------------
// Launch. Inputs: 0=q 1=k 2=v 3=k_b 4=mask 5=scale_w 6=Wb 7=bb 8=Ww 9=bw
// ---------------------------------------------------------------------------
extern "C" void kernel_launch(void* const* d_in, const int* in_sizes, int n_in,
                              void* d_out, int out_size)
{
    const float* q       = (const float*)d_in[0];
    const float* k       = (const float*)d_in[1];
    const float* v       = (const float*)d_in[2];
    const float* k_b     = (const float*)d_in[3];
    const int*   mask    = (const int*)  d_in[4];
    const float* scale_w = (const float*)d_in[5];
    const float* Wb      = (const float*)d_in[6];
    const float* bb      = (const float*)d_in[7];
    const float* Ww      = (const float*)d_in[8];
    const float* bw      = (const float*)d_in[9];
    float* out = (float*)d_out;

    cudaFuncSetAttribute(attn_tc, cudaFuncAttributeMaxDynamicSharedMemorySize,
                         ATTN_SMEM_BYTES);
    cudaFuncSetAttribute(gemm_tc<true>,
                         cudaFuncAttributeMaxDynamicSharedMemorySize, GEMM_SMEM_BYTES);
    cudaFuncSetAttribute(gemm_tc<false>,
                         cudaFuncAttributeMaxDynamicSharedMemorySize, GEMM_SMEM_BYTES);

    // mask all-ones flags + V split/transpose prep
    maskflag<<<B_, 128>>>(mask);
    vprep<<<B_ * NH_ * 32, 128>>>(v);

    // keff = k_b @ Wb^T + bb + k   (written directly as split bf16 words)
    gemm_tc<true><<<dim3(H_ / 64, M_ / 128), 256, GEMM_SMEM_BYTES>>>(
        k_b, Wb, bb, k, nullptr);

    // hidden = attention(q, keff, v)
    attn_tc<<<dim3(L_ / 128, NH_, B_), 256, ATTN_SMEM_BYTES>>>(q, mask, scale_w);

    // out = hidden @ Ww^T + bw
    gemm_tc<false><<<dim3(H_ / 64, M_ / 128), 256, GEMM_SMEM_BYTES>>>(
        nullptr, Ww, bw, nullptr, out);
}

// round 12
// speedup vs baseline: 1.0674x; 1.0674x over previous
#include <cuda_runtime.h>
#include <cstdint>

#define B_  4
#define L_  2048
#define H_  256
#define NH_ 8
#define DH_ 32
#define M_  (B_*L_)   // 8192 rows

// ---------------------------------------------------------------------------
// Global scratch (allocation-free rule: __device__ globals)
// K(eff) split bf16 words, layout [b][h][tile32][key64][16 words] (packed)
// V^T   split bf16 words, layout [b][h][tile32][drow32][36 words] (32 used)
// ---------------------------------------------------------------------------
__device__ __align__(16) uint32_t g_kh[B_*NH_*32*64*16];
__device__ __align__(16) uint32_t g_kl[B_*NH_*32*64*16];
__device__ __align__(16) uint32_t g_vh[B_*NH_*32*32*36];
__device__ __align__(16) uint32_t g_vl[B_*NH_*32*32*36];
__device__ __align__(16) float    g_hidden[M_ * H_];
__device__ int g_mflag[B_];   // 1 = no masked keys in this batch row

// ---------------------------------------------------------------------------
// helpers
// ---------------------------------------------------------------------------
__device__ __forceinline__ float ex2f(float x) {
    float r; asm("ex2.approx.f32 %0, %1;" : "=f"(r) : "f"(x)); return r;
}
__device__ __forceinline__ void mma16(float c[4], const uint32_t a[4],
                                      uint32_t b0, uint32_t b1) {
    asm("mma.sync.aligned.m16n8k16.row.col.f32.bf16.bf16.f32 "
        "{%0,%1,%2,%3},{%4,%5,%6,%7},{%8,%9},{%0,%1,%2,%3};"
        : "+f"(c[0]), "+f"(c[1]), "+f"(c[2]), "+f"(c[3])
        : "r"(a[0]), "r"(a[1]), "r"(a[2]), "r"(a[3]), "r"(b0), "r"(b1));
}
// pack (lo=x, hi=y) into bf16x2; split2 also returns residual word
__device__ __forceinline__ uint32_t packbf(float x, float y) {
    uint32_t r; asm("cvt.rn.bf16x2.f32 %0, %1, %2;" : "=r"(r) : "f"(y), "f"(x));
    return r;
}
__device__ __forceinline__ void split2(float x, float y,
                                       uint32_t& hw, uint32_t& lw) {
    hw = packbf(x, y);
    float xh = __uint_as_float(hw << 16);
    float yh = __uint_as_float(hw & 0xffff0000u);
    lw = packbf(x - xh, y - yh);
}
__device__ __forceinline__ void cp16(uint32_t saddr, const void* gaddr) {
    asm volatile("cp.async.cg.shared.global [%0], [%1], 16;"
                 :: "r"(saddr), "l"(gaddr));
}
__device__ __forceinline__ void cp_commit() {
    asm volatile("cp.async.commit_group;");
}
__device__ __forceinline__ void cp_wait0() {
    asm volatile("cp.async.wait_group 0;" ::: "memory");
}

// word-position permutations: u = w&7, s = w>>3
// K rows have 16 words: pos = (u&3)*4 + 2s + (u>>2)
// V rows have 32 words: pos = (u&3)*8 + 2s + (u>>2)
__device__ __forceinline__ int kpos(int w) {
    return ((w & 3) << 2) + ((w >> 3) << 1) + ((w >> 2) & 1);
}
__device__ __forceinline__ int vpos(int w) {
    return ((w & 3) << 3) + ((w >> 3) << 1) + ((w >> 2) & 1);
}

// ---------------------------------------------------------------------------
// mask flag: g_mflag[b] = 1 iff mask[b][*] all nonzero
// ---------------------------------------------------------------------------
__global__ __launch_bounds__(128)
void maskflag(const int* __restrict__ mask)
{
    __shared__ int s[128];
    const int b = blockIdx.x, tid = threadIdx.x;
    int all1 = 1;
    for (int i = tid; i < L_; i += 128) all1 &= (mask[b * L_ + i] != 0);
    s[tid] = all1;
    __syncthreads();
    for (int st = 64; st; st >>= 1) {
        if (tid < st) s[tid] &= s[tid + st];
        __syncthreads();
    }
    if (tid == 0) g_mflag[b] = s[0];
}

// ---------------------------------------------------------------------------
// V prep: v [b][kv][h*32+d] f32  ->  g_vh/g_vl transposed split words
// ---------------------------------------------------------------------------
__global__ __launch_bounds__(128)
void vprep(const float* __restrict__ v)
{
    __shared__ float sv[64 * 36];
    __shared__ uint32_t swh[32 * 36], swl[32 * 36];
    const int bx = blockIdx.x;
    const int kt = bx & 31, h = (bx >> 5) & 7, b = bx >> 8;
    const int tid = threadIdx.x;
    const float* src = v + ((size_t)(b * L_ + kt * 64)) * H_ + h * 32;

    #pragma unroll
    for (int u = 0; u < 4; u++) {
        int idx = tid + u * 128;
        int row = idx >> 3, c4 = idx & 7;
        *(float4*)&sv[row * 36 + c4 * 4] = *(const float4*)&src[row * H_ + c4 * 4];
    }
    __syncthreads();
    #pragma unroll
    for (int u = 0; u < 8; u++) {
        int idx = tid + u * 128;
        int drow = idx >> 5, w = idx & 31;
        float x = sv[(2 * w) * 36 + drow];
        float y = sv[(2 * w + 1) * 36 + drow];
        uint32_t hw, lw; split2(x, y, hw, lw);
        int p = vpos(w);
        swh[drow * 36 + p] = hw;
        swl[drow * 36 + p] = lw;
    }
    __syncthreads();
    uint32_t* gh = g_vh + (size_t)bx * 1152;
    uint32_t* gl = g_vl + (size_t)bx * 1152;
    #pragma unroll
    for (int u = 0; u < 9; u++) {
        int idx = tid + u * 128;
        if (idx < 1152) { gh[idx] = swh[idx]; gl[idx] = swl[idx]; }
    }
}

// ---------------------------------------------------------------------------
// GEMM (bf16 3x, m16n8k16): out[m,n] = A·W^T + bias (+add). BM=128,BN=64,BK=32.
// smem holds packed bf16x2 hi/lo words, 20-word row stride (16 used).
// Register prefetch of next k-tile overlaps LDG with mma.
// ---------------------------------------------------------------------------
#define GAH 0
#define GAL (128 * 20)
#define GWH (2 * 128 * 20)
#define GWL (2 * 128 * 20 + 64 * 20)
#define GEMM_SMEM_WORDS (2 * 128 * 20 + 2 * 64 * 20)
#define GEMM_SMEM_BYTES (GEMM_SMEM_WORDS * 4)

template<bool KEFF>
__global__ __launch_bounds__(256)
void gemm_tc(const float* __restrict__ Ain,
             const float* __restrict__ W,
             const float* __restrict__ bias,
             const float* __restrict__ add,
             float* __restrict__ outp)
{
    extern __shared__ uint32_t smw[];
    const float* A = KEFF ? Ain : g_hidden;

    const int m0  = blockIdx.y * 128;
    const int n0  = blockIdx.x * 64;
    const int tid = threadIdx.x;
    const int warp   = tid >> 5;
    const int lane   = tid & 31;
    const int warp_m = warp >> 1;
    const int warp_n = warp & 1;
    const int g = lane >> 2;
    const int t = lane & 3;

    float acc[2][4][4] = {};

    float4 xa[4], xw[2];
    #pragma unroll
    for (int u = 0; u < 4; u++) {
        int idx = tid + u * 256;
        xa[u] = *(const float4*)&A[(size_t)(m0 + (idx >> 3)) * H_ + (idx & 7) * 4];
    }
    #pragma unroll
    for (int u = 0; u < 2; u++) {
        int idx = tid + u * 256;
        xw[u] = *(const float4*)&W[(size_t)(n0 + (idx >> 3)) * H_ + (idx & 7) * 4];
    }

    for (int k0 = 0; k0 < H_; k0 += 32) {
        #pragma unroll
        for (int u = 0; u < 4; u++) {
            int idx = tid + u * 256;
            int row = idx >> 3, c4 = idx & 7;
            uint32_t h0, l0, h1, l1;
            split2(xa[u].x, xa[u].y, h0, l0);
            split2(xa[u].z, xa[u].w, h1, l1);
            *(uint2*)&smw[GAH + row * 20 + c4 * 2] = make_uint2(h0, h1);
            *(uint2*)&smw[GAL + row * 20 + c4 * 2] = make_uint2(l0, l1);
        }
        #pragma unroll
        for (int u = 0; u < 2; u++) {
            int idx = tid + u * 256;
            int row = idx >> 3, c4 = idx & 7;
            uint32_t h0, l0, h1, l1;
            split2(xw[u].x, xw[u].y, h0, l0);
            split2(xw[u].z, xw[u].w, h1, l1);
            *(uint2*)&smw[GWH + row * 20 + c4 * 2] = make_uint2(h0, h1);
            *(uint2*)&smw[GWL + row * 20 + c4 * 2] = make_uint2(l0, l1);
        }
        __syncthreads();

        if (k0 + 32 < H_) {
            #pragma unroll
            for (int u = 0; u < 4; u++) {
                int idx = tid + u * 256;
                xa[u] = *(const float4*)&A[(size_t)(m0 + (idx >> 3)) * H_ +
                                           k0 + 32 + (idx & 7) * 4];
            }
            #pragma unroll
            for (int u = 0; u < 2; u++) {
                int idx = tid + u * 256;
                xw[u] = *(const float4*)&W[(size_t)(n0 + (idx >> 3)) * H_ +
                                           k0 + 32 + (idx & 7) * 4];
            }
        }

        #pragma unroll
        for (int s = 0; s < 2; s++) {
            uint32_t ah[2][4], al[2][4];
            #pragma unroll
            for (int mt = 0; mt < 2; mt++) {
                int r0 = (warp_m * 32 + mt * 16 + g) * 20 + 8 * s + t;
                ah[mt][0] = smw[GAH + r0];
                ah[mt][1] = smw[GAH + r0 + 160];      // +8 rows
                ah[mt][2] = smw[GAH + r0 + 4];
                ah[mt][3] = smw[GAH + r0 + 164];
                al[mt][0] = smw[GAL + r0];
                al[mt][1] = smw[GAL + r0 + 160];
                al[mt][2] = smw[GAL + r0 + 4];
                al[mt][3] = smw[GAL + r0 + 164];
            }
            #pragma unroll
            for (int nt = 0; nt < 4; nt++) {
                int rw = (warp_n * 32 + nt * 8 + g) * 20 + 8 * s + t;
                uint32_t wh0 = smw[GWH + rw];
                uint32_t wh1 = smw[GWH + rw + 4];
                uint32_t wl0 = smw[GWL + rw];
                uint32_t wl1 = smw[GWL + rw + 4];
                #pragma unroll
                for (int mt = 0; mt < 2; mt++) {
                    mma16(acc[mt][nt], al[mt], wh0, wh1);
                    mma16(acc[mt][nt], ah[mt], wl0, wl1);
                    mma16(acc[mt][nt], ah[mt], wh0, wh1);
                }
            }
        }
        __syncthreads();
    }

    #pragma unroll
    for (int mt = 0; mt < 2; mt++) {
        #pragma unroll
        for (int nt = 0; nt < 4; nt++) {
            int n  = n0 + warp_n * 32 + nt * 8 + 2 * t;
            int mA = m0 + warp_m * 32 + mt * 16 + g;
            int mB = mA + 8;
            float2 bs = *(const float2*)&bias[n];
            float x0 = acc[mt][nt][0] + bs.x, x1 = acc[mt][nt][1] + bs.y;
            float y0 = acc[mt][nt][2] + bs.x, y1 = acc[mt][nt][3] + bs.y;
            if (KEFF) {
                float2 a0 = *(const float2*)&add[(size_t)mA * H_ + n];
                float2 a1 = *(const float2*)&add[(size_t)mB * H_ + n];
                x0 += a0.x; x1 += a0.y; y0 += a1.x; y1 += a1.y;
                int h = n >> 5;
                int wd = (n & 31) >> 1;
                int p = kpos(wd);
                uint32_t hw, lw;
                {
                    int bi = mA >> 11, l = mA & 2047;
                    size_t base = (((size_t)(bi * NH_ + h) * 32 + (l >> 6)) * 64
                                   + (l & 63)) * 16 + p;
                    split2(x0, x1, hw, lw);
                    g_kh[base] = hw; g_kl[base] = lw;
                }
                {
                    int bi = mB >> 11, l = mB & 2047;
                    size_t base = (((size_t)(bi * NH_ + h) * 32 + (l >> 6)) * 64
                                   + (l & 63)) * 16 + p;
                    split2(y0, y1, hw, lw);
                    g_kh[base] = hw; g_kl[base] = lw;
                }
            } else {
                *(float2*)&outp[(size_t)mA * H_ + n] = make_float2(x0, x1);
                *(float2*)&outp[(size_t)mB * H_ + n] = make_float2(y0, y1);
            }
        }
    }
}

// ---------------------------------------------------------------------------
// Flash attention, bf16x3 via m16n8k16, static softmax in exp2 domain
// (no offset: f32 range absorbs exp2(s') for this problem's bounded logits).
// P lives in registers (S C-fragment == PV A-fragment).
// K rows PACKED at 16-word stride: per-phase LDS banks {0,4,8,12}/{16,20,24,28}
// -> conflict-free (the old 20-stride had a 2-way conflict on every K load).
// BQ=128 (8 warps, 256 threads), BK=64, cp.async double-buffered K/V.
// smem words/buffer: KH 1024 | KL 1024 | VH 1152 | VL 1152 | MS 64 = 4416.
// ---------------------------------------------------------------------------
#define OKH 0
#define OKL 1024
#define OVH 2048
#define OVL 3200
#define OMS 4352
#define BUFSZ 4416
#define ATTN_SMEM_WORDS (2 * BUFSZ)
#define ATTN_SMEM_BYTES (ATTN_SMEM_WORDS * 4)

__device__ __forceinline__ void fill_tile(uint32_t sbase, int bufbase,
                                          int bh, int kt,
                                          const int* __restrict__ maskb)
{
    const int tid = threadIdx.x;
    size_t kb = ((size_t)bh * 32 + kt) * 1024;
    size_t vb = ((size_t)bh * 32 + kt) * 1152;
    const uint32_t* gkh = g_kh + kb;
    const uint32_t* gkl = g_kl + kb;
    const uint32_t* gvh = g_vh + vb;
    const uint32_t* gvl = g_vl + vb;
    {   // K: 1024 words per array = 256 cp16 each; one per thread
        int i = tid * 4;
        cp16(sbase + (bufbase + OKH) * 4 + i * 4, gkh + i);
        cp16(sbase + (bufbase + OKL) * 4 + i * 4, gkl + i);
    }
    #pragma unroll
    for (int u = 0; u < 2; u++) {
        int i = tid + u * 256;
        if (i < 288) {
            cp16(sbase + (bufbase + OVH + i * 4) * 4, gvh + i * 4);
            cp16(sbase + (bufbase + OVL + i * 4) * 4, gvl + i * 4);
        }
    }
    if (tid < 16)
        cp16(sbase + (bufbase + OMS + tid * 4) * 4, maskb + kt * 64 + tid * 4);
    cp_commit();
}

__global__ __launch_bounds__(256)
void attn_tc(const float* __restrict__ q,
             const int*   __restrict__ mask,
             const float* __restrict__ scale_w)
{
    extern __shared__ uint32_t smu[];
    const uint32_t sbase = (uint32_t)__cvta_generic_to_shared(smu);

    const int b   = blockIdx.z;
    const int h   = blockIdx.y;
    const int q0  = blockIdx.x * 128;
    const int bh  = b * NH_ + h;
    const int tid = threadIdx.x;
    const int warp = tid >> 5;
    const int lane = tid & 31;
    const int g = lane >> 2;
    const int t = lane & 3;
    // exp2-domain: fold log2e into the Q pre-scale; p = exp2(s')
    const float rs = 0.17677669529663687f * 1.4426950408889634f;

    const int r0l = warp * 16 + g;
    const int r1l = r0l + 8;
    const int* maskb = mask + b * L_;
    const int noMask = g_mflag[b];

    // ---- Q fragments: 2 k16-steps, split bf16 ----
    const float s0 = scale_w[h * L_ + q0 + r0l] * rs;
    const float s1 = scale_w[h * L_ + q0 + r1l] * rs;
    const float* qb = q + (size_t)(b * L_ + q0) * H_ + h * DH_;

    uint32_t qh[2][4], ql[2][4];
    #pragma unroll
    for (int s = 0; s < 2; s++) {
        float2 v0 = *(const float2*)&qb[r0l * H_ + s * 16 + 2 * t];
        float2 v2 = *(const float2*)&qb[r0l * H_ + s * 16 + 2 * t + 8];
        float2 v1 = *(const float2*)&qb[r1l * H_ + s * 16 + 2 * t];
        float2 v3 = *(const float2*)&qb[r1l * H_ + s * 16 + 2 * t + 8];
        split2(v0.x * s0, v0.y * s0, qh[s][0], ql[s][0]);
        split2(v1.x * s1, v1.y * s1, qh[s][1], ql[s][1]);
        split2(v2.x * s0, v2.y * s0, qh[s][2], ql[s][2]);
        split2(v3.x * s1, v3.y * s1, qh[s][3], ql[s][3]);
    }

    float l0 = 0.f, l1 = 0.f;   // per-thread partial; reduced after the loop
    float o[4][4] = {};

    const int koff = g * 16 + t * 4;           // K fragment base (packed rows)
    const int voff = g * 36 + t * 8;           // V fragment base

    fill_tile(sbase, 0, bh, 0, maskb);

    for (int kt = 0; kt < 32; kt++) {
        const int buf = (kt & 1) ? BUFSZ : 0;
        cp_wait0();
        __syncthreads();
        if (kt + 1 < 32)
            fill_tile(sbase, (kt & 1) ? 0 : BUFSZ, bh, kt + 1, maskb);

        const uint32_t* KH = smu + buf + OKH;
        const uint32_t* KL = smu + buf + OKL;
        const uint32_t* VH = smu + buf + OVH;
        const uint32_t* VL = smu + buf + OVL;
        const int*      MS = (const int*)(smu + buf + OMS);

        // ---- S (bf16x3) in two halves; exp2+pack interleaved ----
        uint32_t APH[4][4], APL[4][4];
        #pragma unroll
        for (int half = 0; half < 2; half++) {
            float c[4][4] = {};
            #pragma unroll
            for (int jj = 0; jj < 4; jj++) {
                int j = half * 4 + jj;
                uint4 bhw = *(const uint4*)(KH + j * 128 + koff);
                uint4 blw = *(const uint4*)(KL + j * 128 + koff);
                mma16(c[jj], qh[0], bhw.x, bhw.y);
                mma16(c[jj], qh[1], bhw.z, bhw.w);
                mma16(c[jj], ql[0], bhw.x, bhw.y);
                mma16(c[jj], ql[1], bhw.z, bhw.w);
                mma16(c[jj], qh[0], blw.x, blw.y);
                mma16(c[jj], qh[1], blw.z, blw.w);
            }
            if (!noMask) {
                #pragma unroll
                for (int jj = 0; jj < 4; jj++) {
                    int j = half * 4 + jj;
                    int2 mv = *(const int2*)(MS + j * 8 + 2 * t);
                    if (mv.x == 0) { c[jj][0] = -1e9f; c[jj][2] = -1e9f; }
                    if (mv.y == 0) { c[jj][1] = -1e9f; c[jj][3] = -1e9f; }
                }
            }
            #pragma unroll
            for (int kb2 = 0; kb2 < 2; kb2++) {
                int kb = half * 2 + kb2;
                float pA0 = ex2f(c[2*kb2][0]);
                float pA1 = ex2f(c[2*kb2][1]);
                float pA2 = ex2f(c[2*kb2][2]);
                float pA3 = ex2f(c[2*kb2][3]);
                float pB0 = ex2f(c[2*kb2+1][0]);
                float pB1 = ex2f(c[2*kb2+1][1]);
                float pB2 = ex2f(c[2*kb2+1][2]);
                float pB3 = ex2f(c[2*kb2+1][3]);
                l0 += pA0 + pA1 + pB0 + pB1;
                l1 += pA2 + pA3 + pB2 + pB3;
                split2(pA0, pA1, APH[kb][0], APL[kb][0]);
                split2(pA2, pA3, APH[kb][1], APL[kb][1]);
                split2(pB0, pB1, APH[kb][2], APL[kb][2]);
                split2(pB2, pB3, APH[kb][3], APL[kb][3]);
            }
        }

        // ---- O += P·V (bf16x3), P from registers ----
        #pragma unroll
        for (int nb = 0; nb < 4; nb++) {
            uint4 vh0 = *(const uint4*)(VH + nb * 288 + voff);
            uint4 vh1 = *(const uint4*)(VH + nb * 288 + voff + 4);
            uint4 vl0 = *(const uint4*)(VL + nb * 288 + voff);
            uint4 vl1 = *(const uint4*)(VL + nb * 288 + voff + 4);
            mma16(o[nb], APH[0], vh0.x, vh0.y);
            mma16(o[nb], APH[1], vh0.z, vh0.w);
            mma16(o[nb], APH[2], vh1.x, vh1.y);
            mma16(o[nb], APH[3], vh1.z, vh1.w);
            mma16(o[nb], APL[0], vh0.x, vh0.y);
            mma16(o[nb], APL[1], vh0.z, vh0.w);
            mma16(o[nb], APL[2], vh1.x, vh1.y);
            mma16(o[nb], APL[3], vh1.z, vh1.w);
            mma16(o[nb], APH[0], vl0.x, vl0.y);
            mma16(o[nb], APH[1], vl0.z, vl0.w);
            mma16(o[nb], APH[2], vl1.x, vl1.y);
            mma16(o[nb], APH[3], vl1.z, vl1.w);
        }
    }

    // ---- one-time l reduction across the 4-lane groups ----
    l0 += __shfl_xor_sync(0xffffffffu, l0, 1);
    l0 += __shfl_xor_sync(0xffffffffu, l0, 2);
    l1 += __shfl_xor_sync(0xffffffffu, l1, 1);
    l1 += __shfl_xor_sync(0xffffffffu, l1, 2);

    // ---- normalize + store (fused head transpose) ----
    float inv0 = 1.f / l0, inv1 = 1.f / l1;
    #pragma unroll
    for (int nb = 0; nb < 4; nb++) {
        int col = h * DH_ + nb * 8 + 2 * t;
        float2 w0 = make_float2(o[nb][0] * inv0, o[nb][1] * inv0);
        float2 w1 = make_float2(o[nb][2] * inv1, o[nb][3] * inv1);
        *(float2*)&g_hidden[(size_t)(b * L_ + q0 + r0l) * H_ + col] = w0;
        *(float2*)&g_hidden[(size_t)(b * L_ + q0 + r1l) * H_ + col] = w1;
    }
}

// ---------------------------------------------------------------------------
// Launch. Inputs: 0=q 1=k 2=v 3=k_b 4=mask 5=scale_w 6=Wb 7=bb 8=Ww 9=bw
// ---------------------------------------------------------------------------
extern "C" void kernel_launch(void* const* d_in, const int* in_sizes, int n_in,
                              void* d_out, int out_size)
{
    const float* q       = (const float*)d_in[0];
    const float* k       = (const float*)d_in[1];
    const float* v       = (const float*)d_in[2];
    const float* k_b     = (const float*)d_in[3];
    const int*   mask    = (const int*)  d_in[4];
    const float* scale_w = (const float*)d_in[5];
    const float* Wb      = (const float*)d_in[6];
    const float* bb      = (const float*)d_in[7];
    const float* Ww      = (const float*)d_in[8];
    const float* bw      = (const float*)d_in[9];
    float* out = (float*)d_out;

    cudaFuncSetAttribute(attn_tc, cudaFuncAttributeMaxDynamicSharedMemorySize,
                         ATTN_SMEM_BYTES);
    cudaFuncSetAttribute(gemm_tc<true>,
                         cudaFuncAttributeMaxDynamicSharedMemorySize, GEMM_SMEM_BYTES);
    cudaFuncSetAttribute(gemm_tc<false>,
                         cudaFuncAttributeMaxDynamicSharedMemorySize, GEMM_SMEM_BYTES);

    // mask all-ones flags + V split/transpose prep
    maskflag<<<B_, 128>>>(mask);
    vprep<<<B_ * NH_ * 32, 128>>>(v);

    // keff = k_b @ Wb^T + bb + k   (written directly as split bf16 words)
    gemm_tc<true><<<dim3(H_ / 64, M_ / 128), 256, GEMM_SMEM_BYTES>>>(
        k_b, Wb, bb, k, nullptr);

    // hidden = attention(q, keff, v)
    attn_tc<<<dim3(L_ / 128, NH_, B_), 256, ATTN_SMEM_BYTES>>>(q, mask, scale_w);

    // out = hidden @ Ww^T + bw
    gemm_tc<false><<<dim3(H_ / 64, M_ / 128), 256, GEMM_SMEM_BYTES>>>(
        nullptr, Ww, bw, nullptr, out);
}

// round 13
// speedup vs baseline: 1.2183x; 1.1414x over previous
#include <cuda_runtime.h>
#include <cuda_fp16.h>
#include <cstdint>

#define B_  4
#define L_  2048
#define H_  256
#define NH_ 8
#define DH_ 32
#define M_  (B_*L_)   // 8192 rows

// ---------------------------------------------------------------------------
// Global scratch (allocation-free rule: __device__ globals)
// K(eff) fp16 words (single, unsplit), [b][h][tile32][key64][16 words]
// V^T split bf16 words, [b][h][tile32][drow32][36 words] (32 used)
// ---------------------------------------------------------------------------
__device__ __align__(16) uint32_t g_kh[B_*NH_*32*64*16];
__device__ __align__(16) uint32_t g_vh[B_*NH_*32*32*36];
__device__ __align__(16) uint32_t g_vl[B_*NH_*32*32*36];
__device__ __align__(16) float    g_hidden[M_ * H_];
__device__ int g_mflag[B_];   // 1 = no masked keys in this batch row

// ---------------------------------------------------------------------------
// helpers
// ---------------------------------------------------------------------------
__device__ __forceinline__ float ex2f(float x) {
    float r; asm("ex2.approx.f32 %0, %1;" : "=f"(r) : "f"(x)); return r;
}
// bf16 mma (PV + output GEMM)
__device__ __forceinline__ void mma16(float c[4], const uint32_t a[4],
                                      uint32_t b0, uint32_t b1) {
    asm("mma.sync.aligned.m16n8k16.row.col.f32.bf16.bf16.f32 "
        "{%0,%1,%2,%3},{%4,%5,%6,%7},{%8,%9},{%0,%1,%2,%3};"
        : "+f"(c[0]), "+f"(c[1]), "+f"(c[2]), "+f"(c[3])
        : "r"(a[0]), "r"(a[1]), "r"(a[2]), "r"(a[3]), "r"(b0), "r"(b1));
}
// fp16 mma (S + keff GEMM)
__device__ __forceinline__ void mma16h(float c[4], const uint32_t a[4],
                                       uint32_t b0, uint32_t b1) {
    asm("mma.sync.aligned.m16n8k16.row.col.f32.f16.f16.f32 "
        "{%0,%1,%2,%3},{%4,%5,%6,%7},{%8,%9},{%0,%1,%2,%3};"
        : "+f"(c[0]), "+f"(c[1]), "+f"(c[2]), "+f"(c[3])
        : "r"(a[0]), "r"(a[1]), "r"(a[2]), "r"(a[3]), "r"(b0), "r"(b1));
}
// bf16 pack/split
__device__ __forceinline__ uint32_t packbf(float x, float y) {
    uint32_t r; asm("cvt.rn.bf16x2.f32 %0, %1, %2;" : "=r"(r) : "f"(y), "f"(x));
    return r;
}
__device__ __forceinline__ void split2(float x, float y,
                                       uint32_t& hw, uint32_t& lw) {
    hw = packbf(x, y);
    float xh = __uint_as_float(hw << 16);
    float yh = __uint_as_float(hw & 0xffff0000u);
    lw = packbf(x - xh, y - yh);
}
// fp16 pack/split
__device__ __forceinline__ uint32_t packh(float x, float y) {
    uint32_t r; asm("cvt.rn.f16x2.f32 %0, %1, %2;" : "=r"(r) : "f"(y), "f"(x));
    return r;
}
__device__ __forceinline__ void split2h(float x, float y,
                                        uint32_t& hw, uint32_t& lw) {
    hw = packh(x, y);
    __half2 h2 = *reinterpret_cast<__half2*>(&hw);
    float xh = __half2float(__low2half(h2));
    float yh = __half2float(__high2half(h2));
    lw = packh(x - xh, y - yh);
}
__device__ __forceinline__ void cp16(uint32_t saddr, const void* gaddr) {
    asm volatile("cp.async.cg.shared.global [%0], [%1], 16;"
                 :: "r"(saddr), "l"(gaddr));
}
__device__ __forceinline__ void cp_commit() {
    asm volatile("cp.async.commit_group;");
}
__device__ __forceinline__ void cp_wait0() {
    asm volatile("cp.async.wait_group 0;" ::: "memory");
}

// word-position permutations: u = w&7, s = w>>3
// K rows have 16 words: pos = (u&3)*4 + 2s + (u>>2)
// V rows have 32 words: pos = (u&3)*8 + 2s + (u>>2)
__device__ __forceinline__ int kpos(int w) {
    return ((w & 3) << 2) + ((w >> 3) << 1) + ((w >> 2) & 1);
}
__device__ __forceinline__ int vpos(int w) {
    return ((w & 3) << 3) + ((w >> 3) << 1) + ((w >> 2) & 1);
}

// ---------------------------------------------------------------------------
// mask flag: g_mflag[b] = 1 iff mask[b][*] all nonzero
// ---------------------------------------------------------------------------
__global__ __launch_bounds__(128)
void maskflag(const int* __restrict__ mask)
{
    __shared__ int s[128];
    const int b = blockIdx.x, tid = threadIdx.x;
    int all1 = 1;
    for (int i = tid; i < L_; i += 128) all1 &= (mask[b * L_ + i] != 0);
    s[tid] = all1;
    __syncthreads();
    for (int st = 64; st; st >>= 1) {
        if (tid < st) s[tid] &= s[tid + st];
        __syncthreads();
    }
    if (tid == 0) g_mflag[b] = s[0];
}

// ---------------------------------------------------------------------------
// V prep: v [b][kv][h*32+d] f32  ->  g_vh/g_vl transposed split bf16 words
// ---------------------------------------------------------------------------
__global__ __launch_bounds__(128)
void vprep(const float* __restrict__ v)
{
    __shared__ float sv[64 * 36];
    __shared__ uint32_t swh[32 * 36], swl[32 * 36];
    const int bx = blockIdx.x;
    const int kt = bx & 31, h = (bx >> 5) & 7, b = bx >> 8;
    const int tid = threadIdx.x;
    const float* src = v + ((size_t)(b * L_ + kt * 64)) * H_ + h * 32;

    #pragma unroll
    for (int u = 0; u < 4; u++) {
        int idx = tid + u * 128;
        int row = idx >> 3, c4 = idx & 7;
        *(float4*)&sv[row * 36 + c4 * 4] = *(const float4*)&src[row * H_ + c4 * 4];
    }
    __syncthreads();
    #pragma unroll
    for (int u = 0; u < 8; u++) {
        int idx = tid + u * 128;
        int drow = idx >> 5, w = idx & 31;
        float x = sv[(2 * w) * 36 + drow];
        float y = sv[(2 * w + 1) * 36 + drow];
        uint32_t hw, lw; split2(x, y, hw, lw);
        int p = vpos(w);
        swh[drow * 36 + p] = hw;
        swl[drow * 36 + p] = lw;
    }
    __syncthreads();
    uint32_t* gh = g_vh + (size_t)bx * 1152;
    uint32_t* gl = g_vl + (size_t)bx * 1152;
    #pragma unroll
    for (int u = 0; u < 9; u++) {
        int idx = tid + u * 128;
        if (idx < 1152) { gh[idx] = swh[idx]; gl[idx] = swl[idx]; }
    }
}

// ---------------------------------------------------------------------------
// GEMM1 (fp16 2x): keff = k_b @ Wb^T + bb + k, written as fp16 K image.
// A split fp16 (hi+lo), W single fp16. BM=128,BN=64,BK=32, 64 mma/k-iter.
// ---------------------------------------------------------------------------
#define KAH 0
#define KAL (128 * 20)
#define KWH (2 * 128 * 20)
#define GK_SMEM_WORDS (2 * 128 * 20 + 64 * 20)
#define GK_SMEM_BYTES (GK_SMEM_WORDS * 4)

__global__ __launch_bounds__(256)
void gemm_keff(const float* __restrict__ Ain,
               const float* __restrict__ W,
               const float* __restrict__ bias,
               const float* __restrict__ add)
{
    extern __shared__ uint32_t smw[];
    const int m0  = blockIdx.y * 128;
    const int n0  = blockIdx.x * 64;
    const int tid = threadIdx.x;
    const int warp   = tid >> 5;
    const int lane   = tid & 31;
    const int warp_m = warp >> 1;
    const int warp_n = warp & 1;
    const int g = lane >> 2;
    const int t = lane & 3;

    float acc[2][4][4] = {};

    float4 xa[4], xw[2];
    #pragma unroll
    for (int u = 0; u < 4; u++) {
        int idx = tid + u * 256;
        xa[u] = *(const float4*)&Ain[(size_t)(m0 + (idx >> 3)) * H_ + (idx & 7) * 4];
    }
    #pragma unroll
    for (int u = 0; u < 2; u++) {
        int idx = tid + u * 256;
        xw[u] = *(const float4*)&W[(size_t)(n0 + (idx >> 3)) * H_ + (idx & 7) * 4];
    }

    for (int k0 = 0; k0 < H_; k0 += 32) {
        #pragma unroll
        for (int u = 0; u < 4; u++) {
            int idx = tid + u * 256;
            int row = idx >> 3, c4 = idx & 7;
            uint32_t h0, l0, h1, l1;
            split2h(xa[u].x, xa[u].y, h0, l0);
            split2h(xa[u].z, xa[u].w, h1, l1);
            *(uint2*)&smw[KAH + row * 20 + c4 * 2] = make_uint2(h0, h1);
            *(uint2*)&smw[KAL + row * 20 + c4 * 2] = make_uint2(l0, l1);
        }
        #pragma unroll
        for (int u = 0; u < 2; u++) {
            int idx = tid + u * 256;
            int row = idx >> 3, c4 = idx & 7;
            uint32_t h0 = packh(xw[u].x, xw[u].y);
            uint32_t h1 = packh(xw[u].z, xw[u].w);
            *(uint2*)&smw[KWH + row * 20 + c4 * 2] = make_uint2(h0, h1);
        }
        __syncthreads();

        if (k0 + 32 < H_) {
            #pragma unroll
            for (int u = 0; u < 4; u++) {
                int idx = tid + u * 256;
                xa[u] = *(const float4*)&Ain[(size_t)(m0 + (idx >> 3)) * H_ +
                                             k0 + 32 + (idx & 7) * 4];
            }
            #pragma unroll
            for (int u = 0; u < 2; u++) {
                int idx = tid + u * 256;
                xw[u] = *(const float4*)&W[(size_t)(n0 + (idx >> 3)) * H_ +
                                           k0 + 32 + (idx & 7) * 4];
            }
        }

        #pragma unroll
        for (int s = 0; s < 2; s++) {
            uint32_t ah[2][4], al[2][4];
            #pragma unroll
            for (int mt = 0; mt < 2; mt++) {
                int r0 = (warp_m * 32 + mt * 16 + g) * 20 + 8 * s + t;
                ah[mt][0] = smw[KAH + r0];
                ah[mt][1] = smw[KAH + r0 + 160];
                ah[mt][2] = smw[KAH + r0 + 4];
                ah[mt][3] = smw[KAH + r0 + 164];
                al[mt][0] = smw[KAL + r0];
                al[mt][1] = smw[KAL + r0 + 160];
                al[mt][2] = smw[KAL + r0 + 4];
                al[mt][3] = smw[KAL + r0 + 164];
            }
            #pragma unroll
            for (int nt = 0; nt < 4; nt++) {
                int rw = (warp_n * 32 + nt * 8 + g) * 20 + 8 * s + t;
                uint32_t wh0 = smw[KWH + rw];
                uint32_t wh1 = smw[KWH + rw + 4];
                #pragma unroll
                for (int mt = 0; mt < 2; mt++) {
                    mma16h(acc[mt][nt], al[mt], wh0, wh1);
                    mma16h(acc[mt][nt], ah[mt], wh0, wh1);
                }
            }
        }
        __syncthreads();
    }

    #pragma unroll
    for (int mt = 0; mt < 2; mt++) {
        #pragma unroll
        for (int nt = 0; nt < 4; nt++) {
            int n  = n0 + warp_n * 32 + nt * 8 + 2 * t;
            int mA = m0 + warp_m * 32 + mt * 16 + g;
            int mB = mA + 8;
            float2 bs = *(const float2*)&bias[n];
            float x0 = acc[mt][nt][0] + bs.x, x1 = acc[mt][nt][1] + bs.y;
            float y0 = acc[mt][nt][2] + bs.x, y1 = acc[mt][nt][3] + bs.y;
            float2 a0 = *(const float2*)&add[(size_t)mA * H_ + n];
            float2 a1 = *(const float2*)&add[(size_t)mB * H_ + n];
            x0 += a0.x; x1 += a0.y; y0 += a1.x; y1 += a1.y;
            int h = n >> 5;
            int wd = (n & 31) >> 1;
            int p = kpos(wd);
            {
                int bi = mA >> 11, l = mA & 2047;
                size_t base = (((size_t)(bi * NH_ + h) * 32 + (l >> 6)) * 64
                               + (l & 63)) * 16 + p;
                g_kh[base] = packh(x0, x1);
            }
            {
                int bi = mB >> 11, l = mB & 2047;
                size_t base = (((size_t)(bi * NH_ + h) * 32 + (l >> 6)) * 64
                               + (l & 63)) * 16 + p;
                g_kh[base] = packh(y0, y1);
            }
        }
    }
}

// ---------------------------------------------------------------------------
// GEMM2 (bf16 3x, unchanged): out = hidden @ Ww^T + bw
// ---------------------------------------------------------------------------
#define GAH 0
#define GAL (128 * 20)
#define GWH (2 * 128 * 20)
#define GWL (2 * 128 * 20 + 64 * 20)
#define GEMM_SMEM_WORDS (2 * 128 * 20 + 2 * 64 * 20)
#define GEMM_SMEM_BYTES (GEMM_SMEM_WORDS * 4)

__global__ __launch_bounds__(256)
void gemm_out(const float* __restrict__ W,
              const float* __restrict__ bias,
              float* __restrict__ outp)
{
    extern __shared__ uint32_t smw[];
    const float* A = g_hidden;

    const int m0  = blockIdx.y * 128;
    const int n0  = blockIdx.x * 64;
    const int tid = threadIdx.x;
    const int warp   = tid >> 5;
    const int lane   = tid & 31;
    const int warp_m = warp >> 1;
    const int warp_n = warp & 1;
    const int g = lane >> 2;
    const int t = lane & 3;

    float acc[2][4][4] = {};

    float4 xa[4], xw[2];
    #pragma unroll
    for (int u = 0; u < 4; u++) {
        int idx = tid + u * 256;
        xa[u] = *(const float4*)&A[(size_t)(m0 + (idx >> 3)) * H_ + (idx & 7) * 4];
    }
    #pragma unroll
    for (int u = 0; u < 2; u++) {
        int idx = tid + u * 256;
        xw[u] = *(const float4*)&W[(size_t)(n0 + (idx >> 3)) * H_ + (idx & 7) * 4];
    }

    for (int k0 = 0; k0 < H_; k0 += 32) {
        #pragma unroll
        for (int u = 0; u < 4; u++) {
            int idx = tid + u * 256;
            int row = idx >> 3, c4 = idx & 7;
            uint32_t h0, l0, h1, l1;
            split2(xa[u].x, xa[u].y, h0, l0);
            split2(xa[u].z, xa[u].w, h1, l1);
            *(uint2*)&smw[GAH + row * 20 + c4 * 2] = make_uint2(h0, h1);
            *(uint2*)&smw[GAL + row * 20 + c4 * 2] = make_uint2(l0, l1);
        }
        #pragma unroll
        for (int u = 0; u < 2; u++) {
            int idx = tid + u * 256;
            int row = idx >> 3, c4 = idx & 7;
            uint32_t h0, l0, h1, l1;
            split2(xw[u].x, xw[u].y, h0, l0);
            split2(xw[u].z, xw[u].w, h1, l1);
            *(uint2*)&smw[GWH + row * 20 + c4 * 2] = make_uint2(h0, h1);
            *(uint2*)&smw[GWL + row * 20 + c4 * 2] = make_uint2(l0, l1);
        }
        __syncthreads();

        if (k0 + 32 < H_) {
            #pragma unroll
            for (int u = 0; u < 4; u++) {
                int idx = tid + u * 256;
                xa[u] = *(const float4*)&A[(size_t)(m0 + (idx >> 3)) * H_ +
                                           k0 + 32 + (idx & 7) * 4];
            }
            #pragma unroll
            for (int u = 0; u < 2; u++) {
                int idx = tid + u * 256;
                xw[u] = *(const float4*)&W[(size_t)(n0 + (idx >> 3)) * H_ +
                                           k0 + 32 + (idx & 7) * 4];
            }
        }

        #pragma unroll
        for (int s = 0; s < 2; s++) {
            uint32_t ah[2][4], al[2][4];
            #pragma unroll
            for (int mt = 0; mt < 2; mt++) {
                int r0 = (warp_m * 32 + mt * 16 + g) * 20 + 8 * s + t;
                ah[mt][0] = smw[GAH + r0];
                ah[mt][1] = smw[GAH + r0 + 160];
                ah[mt][2] = smw[GAH + r0 + 4];
                ah[mt][3] = smw[GAH + r0 + 164];
                al[mt][0] = smw[GAL + r0];
                al[mt][1] = smw[GAL + r0 + 160];
                al[mt][2] = smw[GAL + r0 + 4];
                al[mt][3] = smw[GAL + r0 + 164];
            }
            #pragma unroll
            for (int nt = 0; nt < 4; nt++) {
                int rw = (warp_n * 32 + nt * 8 + g) * 20 + 8 * s + t;
                uint32_t wh0 = smw[GWH + rw];
                uint32_t wh1 = smw[GWH + rw + 4];
                uint32_t wl0 = smw[GWL + rw];
                uint32_t wl1 = smw[GWL + rw + 4];
                #pragma unroll
                for (int mt = 0; mt < 2; mt++) {
                    mma16(acc[mt][nt], al[mt], wh0, wh1);
                    mma16(acc[mt][nt], ah[mt], wl0, wl1);
                    mma16(acc[mt][nt], ah[mt], wh0, wh1);
                }
            }
        }
        __syncthreads();
    }

    #pragma unroll
    for (int mt = 0; mt < 2; mt++) {
        #pragma unroll
        for (int nt = 0; nt < 4; nt++) {
            int n  = n0 + warp_n * 32 + nt * 8 + 2 * t;
            int mA = m0 + warp_m * 32 + mt * 16 + g;
            int mB = mA + 8;
            float2 bs = *(const float2*)&bias[n];
            *(float2*)&outp[(size_t)mA * H_ + n] =
                make_float2(acc[mt][nt][0] + bs.x, acc[mt][nt][1] + bs.y);
            *(float2*)&outp[(size_t)mB * H_ + n] =
                make_float2(acc[mt][nt][2] + bs.x, acc[mt][nt][3] + bs.y);
        }
    }
}

// ---------------------------------------------------------------------------
// Flash attention: S in fp16 (Q 2x-split, K single fp16; 4 mma/j),
// PV in bf16x3 (P/V split), static softmax in exp2 domain, P in registers.
// K rows packed 16 words (conflict-free). BQ=128, 256 thr, double-buffered.
// smem words/buffer: KH 1024 | VH 1152 | VL 1152 | MS 64 = 3392.
// ---------------------------------------------------------------------------
#define OKH 0
#define OVH 1024
#define OVL 2176
#define OMS 3328
#define BUFSZ 3392
#define ATTN_SMEM_WORDS (2 * BUFSZ)
#define ATTN_SMEM_BYTES (ATTN_SMEM_WORDS * 4)

__device__ __forceinline__ void fill_tile(uint32_t sbase, int bufbase,
                                          int bh, int kt,
                                          const int* __restrict__ maskb)
{
    const int tid = threadIdx.x;
    size_t kb = ((size_t)bh * 32 + kt) * 1024;
    size_t vb = ((size_t)bh * 32 + kt) * 1152;
    const uint32_t* gkh = g_kh + kb;
    const uint32_t* gvh = g_vh + vb;
    const uint32_t* gvl = g_vl + vb;
    {   // K: 1024 words = 256 cp16; one per thread
        int i = tid * 4;
        cp16(sbase + (bufbase + OKH) * 4 + i * 4, gkh + i);
    }
    #pragma unroll
    for (int u = 0; u < 2; u++) {
        int i = tid + u * 256;
        if (i < 288) {
            cp16(sbase + (bufbase + OVH + i * 4) * 4, gvh + i * 4);
            cp16(sbase + (bufbase + OVL + i * 4) * 4, gvl + i * 4);
        }
    }
    if (tid < 16)
        cp16(sbase + (bufbase + OMS + tid * 4) * 4, maskb + kt * 64 + tid * 4);
    cp_commit();
}

__global__ __launch_bounds__(256)
void attn_tc(const float* __restrict__ q,
             const int*   __restrict__ mask,
             const float* __restrict__ scale_w)
{
    extern __shared__ uint32_t smu[];
    const uint32_t sbase = (uint32_t)__cvta_generic_to_shared(smu);

    const int b   = blockIdx.z;
    const int h   = blockIdx.y;
    const int q0  = blockIdx.x * 128;
    const int bh  = b * NH_ + h;
    const int tid = threadIdx.x;
    const int warp = tid >> 5;
    const int lane = tid & 31;
    const int g = lane >> 2;
    const int t = lane & 3;
    // exp2-domain: fold log2e into the Q pre-scale; p = exp2(s')
    const float rs = 0.17677669529663687f * 1.4426950408889634f;

    const int r0l = warp * 16 + g;
    const int r1l = r0l + 8;
    const int* maskb = mask + b * L_;
    const int noMask = g_mflag[b];

    // ---- Q fragments: 2 k16-steps, split fp16 (22-bit Q) ----
    const float s0 = scale_w[h * L_ + q0 + r0l] * rs;
    const float s1 = scale_w[h * L_ + q0 + r1l] * rs;
    const float* qb = q + (size_t)(b * L_ + q0) * H_ + h * DH_;

    uint32_t qh2[2][4], ql2[2][4];
    #pragma unroll
    for (int s = 0; s < 2; s++) {
        float2 v0 = *(const float2*)&qb[r0l * H_ + s * 16 + 2 * t];
        float2 v2 = *(const float2*)&qb[r0l * H_ + s * 16 + 2 * t + 8];
        float2 v1 = *(const float2*)&qb[r1l * H_ + s * 16 + 2 * t];
        float2 v3 = *(const float2*)&qb[r1l * H_ + s * 16 + 2 * t + 8];
        split2h(v0.x * s0, v0.y * s0, qh2[s][0], ql2[s][0]);
        split2h(v1.x * s1, v1.y * s1, qh2[s][1], ql2[s][1]);
        split2h(v2.x * s0, v2.y * s0, qh2[s][2], ql2[s][2]);
        split2h(v3.x * s1, v3.y * s1, qh2[s][3], ql2[s][3]);
    }

    float l0 = 0.f, l1 = 0.f;   // per-thread partial; reduced after the loop
    float o[4][4] = {};

    const int koff = g * 16 + t * 4;           // K fragment base (packed rows)
    const int voff = g * 36 + t * 8;           // V fragment base

    fill_tile(sbase, 0, bh, 0, maskb);

    for (int kt = 0; kt < 32; kt++) {
        const int buf = (kt & 1) ? BUFSZ : 0;
        cp_wait0();
        __syncthreads();
        if (kt + 1 < 32)
            fill_tile(sbase, (kt & 1) ? 0 : BUFSZ, bh, kt + 1, maskb);

        const uint32_t* KH = smu + buf + OKH;
        const uint32_t* VH = smu + buf + OVH;
        const uint32_t* VL = smu + buf + OVL;
        const int*      MS = (const int*)(smu + buf + OMS);

        // ---- S (fp16 2x) in two halves; exp2+pack interleaved ----
        uint32_t APH[4][4], APL[4][4];
        #pragma unroll
        for (int half = 0; half < 2; half++) {
            float c[4][4] = {};
            #pragma unroll
            for (int jj = 0; jj < 4; jj++) {
                int j = half * 4 + jj;
                uint4 bhw = *(const uint4*)(KH + j * 128 + koff);
                mma16h(c[jj], qh2[0], bhw.x, bhw.y);
                mma16h(c[jj], qh2[1], bhw.z, bhw.w);
                mma16h(c[jj], ql2[0], bhw.x, bhw.y);
                mma16h(c[jj], ql2[1], bhw.z, bhw.w);
            }
            if (!noMask) {
                #pragma unroll
                for (int jj = 0; jj < 4; jj++) {
                    int j = half * 4 + jj;
                    int2 mv = *(const int2*)(MS + j * 8 + 2 * t);
                    if (mv.x == 0) { c[jj][0] = -1e9f; c[jj][2] = -1e9f; }
                    if (mv.y == 0) { c[jj][1] = -1e9f; c[jj][3] = -1e9f; }
                }
            }
            #pragma unroll
            for (int kb2 = 0; kb2 < 2; kb2++) {
                int kb = half * 2 + kb2;
                float pA0 = ex2f(c[2*kb2][0]);
                float pA1 = ex2f(c[2*kb2][1]);
                float pA2 = ex2f(c[2*kb2][2]);
                float pA3 = ex2f(c[2*kb2][3]);
                float pB0 = ex2f(c[2*kb2+1][0]);
                float pB1 = ex2f(c[2*kb2+1][1]);
                float pB2 = ex2f(c[2*kb2+1][2]);
                float pB3 = ex2f(c[2*kb2+1][3]);
                l0 += pA0 + pA1 + pB0 + pB1;
                l1 += pA2 + pA3 + pB2 + pB3;
                split2(pA0, pA1, APH[kb][0], APL[kb][0]);
                split2(pA2, pA3, APH[kb][1], APL[kb][1]);
                split2(pB0, pB1, APH[kb][2], APL[kb][2]);
                split2(pB2, pB3, APH[kb][3], APL[kb][3]);
            }
        }

        // ---- O += P·V (bf16x3), P from registers ----
        #pragma unroll
        for (int nb = 0; nb < 4; nb++) {
            uint4 vh0 = *(const uint4*)(VH + nb * 288 + voff);
            uint4 vh1 = *(const uint4*)(VH + nb * 288 + voff + 4);
            uint4 vl0 = *(const uint4*)(VL + nb * 288 + voff);
            uint4 vl1 = *(const uint4*)(VL + nb * 288 + voff + 4);
            mma16(o[nb], APH[0], vh0.x, vh0.y);
            mma16(o[nb], APH[1], vh0.z, vh0.w);
            mma16(o[nb], APH[2], vh1.x, vh1.y);
            mma16(o[nb], APH[3], vh1.z, vh1.w);
            mma16(o[nb], APL[0], vh0.x, vh0.y);
            mma16(o[nb], APL[1], vh0.z, vh0.w);
            mma16(o[nb], APL[2], vh1.x, vh1.y);
            mma16(o[nb], APL[3], vh1.z, vh1.w);
            mma16(o[nb], APH[0], vl0.x, vl0.y);
            mma16(o[nb], APH[1], vl0.z, vl0.w);
            mma16(o[nb], APH[2], vl1.x, vl1.y);
            mma16(o[nb], APH[3], vl1.z, vl1.w);
        }
    }

    // ---- one-time l reduction across the 4-lane groups ----
    l0 += __shfl_xor_sync(0xffffffffu, l0, 1);
    l0 += __shfl_xor_sync(0xffffffffu, l0, 2);
    l1 += __shfl_xor_sync(0xffffffffu, l1, 1);
    l1 += __shfl_xor_sync(0xffffffffu, l1, 2);

    // ---- normalize + store (fused head transpose) ----
    float inv0 = 1.f / l0, inv1 = 1.f / l1;
    #pragma unroll
    for (int nb = 0; nb < 4; nb++) {
        int col = h * DH_ + nb * 8 + 2 * t;
        float2 w0 = make_float2(o[nb][0] * inv0, o[nb][1] * inv0);
        float2 w1 = make_float2(o[nb][2] * inv1, o[nb][3] * inv1);
        *(float2*)&g_hidden[(size_t)(b * L_ + q0 + r0l) * H_ + col] = w0;
        *(float2*)&g_hidden[(size_t)(b * L_ + q0 + r1l) * H_ + col] = w1;
    }
}

// ---------------------------------------------------------------------------
// Launch. Inputs: 0=q 1=k 2=v 3=k_b 4=mask 5=scale_w 6=Wb 7=bb 8=Ww 9=bw
// ---------------------------------------------------------------------------
extern "C" void kernel_launch(void* const* d_in, const int* in_sizes, int n_in,
                              void* d_out, int out_size)
{
    const float* q       = (const float*)d_in[0];
    const float* k       = (const float*)d_in[1];
    const float* v       = (const float*)d_in[2];
    const float* k_b     = (const float*)d_in[3];
    const int*   mask    = (const int*)  d_in[4];
    const float* scale_w = (const float*)d_in[5];
    const float* Wb      = (const float*)d_in[6];
    const float* bb      = (const float*)d_in[7];
    const float* Ww      = (const float*)d_in[8];
    const float* bw      = (const float*)d_in[9];
    float* out = (float*)d_out;

    cudaFuncSetAttribute(attn_tc, cudaFuncAttributeMaxDynamicSharedMemorySize,
                         ATTN_SMEM_BYTES);
    cudaFuncSetAttribute(gemm_keff,
                         cudaFuncAttributeMaxDynamicSharedMemorySize, GK_SMEM_BYTES);
    cudaFuncSetAttribute(gemm_out,
                         cudaFuncAttributeMaxDynamicSharedMemorySize, GEMM_SMEM_BYTES);

    // mask all-ones flags + V split/transpose prep
    maskflag<<<B_, 128>>>(mask);
    vprep<<<B_ * NH_ * 32, 128>>>(v);

    // keff = k_b @ Wb^T + bb + k   (written directly as fp16 K image)
    gemm_keff<<<dim3(H_ / 64, M_ / 128), 256, GK_SMEM_BYTES>>>(k_b, Wb, bb, k);

    // hidden = attention(q, keff, v)
    attn_tc<<<dim3(L_ / 128, NH_, B_), 256, ATTN_SMEM_BYTES>>>(q, mask, scale_w);

    // out = hidden @ Ww^T + bw
    gemm_out<<<dim3(H_ / 64, M_ / 128), 256, GEMM_SMEM_BYTES>>>(Ww, bw, out);
}

// round 14
// speedup vs baseline: 1.2211x; 1.0022x over previous
#include <cuda_runtime.h>
#include <cuda_fp16.h>
#include <cstdint>

#define B_  4
#define L_  2048
#define H_  256
#define NH_ 8
#define DH_ 32
#define M_  (B_*L_)   // 8192 rows

// ---------------------------------------------------------------------------
// Global scratch (allocation-free rule: __device__ globals)
// K(eff) fp16 words (single, unsplit), [b][h][tile32][key64][16 words]
// V^T split bf16 words, [b][h][tile32][drow32][36 words] (32 used)
// ---------------------------------------------------------------------------
__device__ __align__(16) uint32_t g_kh[B_*NH_*32*64*16];
__device__ __align__(16) uint32_t g_vh[B_*NH_*32*32*36];
__device__ __align__(16) uint32_t g_vl[B_*NH_*32*32*36];
__device__ __align__(16) float    g_hidden[M_ * H_];
__device__ int g_mflag[B_];   // 1 = no masked keys in this batch row

// ---------------------------------------------------------------------------
// helpers
// ---------------------------------------------------------------------------
__device__ __forceinline__ float ex2f(float x) {
    float r; asm("ex2.approx.f32 %0, %1;" : "=f"(r) : "f"(x)); return r;
}
// bf16 mma (PV + output GEMM)
__device__ __forceinline__ void mma16(float c[4], const uint32_t a[4],
                                      uint32_t b0, uint32_t b1) {
    asm("mma.sync.aligned.m16n8k16.row.col.f32.bf16.bf16.f32 "
        "{%0,%1,%2,%3},{%4,%5,%6,%7},{%8,%9},{%0,%1,%2,%3};"
        : "+f"(c[0]), "+f"(c[1]), "+f"(c[2]), "+f"(c[3])
        : "r"(a[0]), "r"(a[1]), "r"(a[2]), "r"(a[3]), "r"(b0), "r"(b1));
}
// fp16 mma (S + keff GEMM)
__device__ __forceinline__ void mma16h(float c[4], const uint32_t a[4],
                                       uint32_t b0, uint32_t b1) {
    asm("mma.sync.aligned.m16n8k16.row.col.f32.f16.f16.f32 "
        "{%0,%1,%2,%3},{%4,%5,%6,%7},{%8,%9},{%0,%1,%2,%3};"
        : "+f"(c[0]), "+f"(c[1]), "+f"(c[2]), "+f"(c[3])
        : "r"(a[0]), "r"(a[1]), "r"(a[2]), "r"(a[3]), "r"(b0), "r"(b1));
}
// bf16 pack/split
__device__ __forceinline__ uint32_t packbf(float x, float y) {
    uint32_t r; asm("cvt.rn.bf16x2.f32 %0, %1, %2;" : "=r"(r) : "f"(y), "f"(x));
    return r;
}
__device__ __forceinline__ void split2(float x, float y,
                                       uint32_t& hw, uint32_t& lw) {
    hw = packbf(x, y);
    float xh = __uint_as_float(hw << 16);
    float yh = __uint_as_float(hw & 0xffff0000u);
    lw = packbf(x - xh, y - yh);
}
// fp16 pack/split
__device__ __forceinline__ uint32_t packh(float x, float y) {
    uint32_t r; asm("cvt.rn.f16x2.f32 %0, %1, %2;" : "=r"(r) : "f"(y), "f"(x));
    return r;
}
__device__ __forceinline__ void split2h(float x, float y,
                                        uint32_t& hw, uint32_t& lw) {
    hw = packh(x, y);
    __half2 h2 = *reinterpret_cast<__half2*>(&hw);
    float xh = __half2float(__low2half(h2));
    float yh = __half2float(__high2half(h2));
    lw = packh(x - xh, y - yh);
}
__device__ __forceinline__ void cp16(uint32_t saddr, const void* gaddr) {
    asm volatile("cp.async.cg.shared.global [%0], [%1], 16;"
                 :: "r"(saddr), "l"(gaddr));
}
__device__ __forceinline__ void cp_commit() {
    asm volatile("cp.async.commit_group;");
}
__device__ __forceinline__ void cp_wait0() {
    asm volatile("cp.async.wait_group 0;" ::: "memory");
}

// word-position permutations: u = w&7, s = w>>3
// K rows have 16 words: pos = (u&3)*4 + 2s + (u>>2)
// V rows have 32 words: pos = (u&3)*8 + 2s + (u>>2)
__device__ __forceinline__ int kpos(int w) {
    return ((w & 3) << 2) + ((w >> 3) << 1) + ((w >> 2) & 1);
}
__device__ __forceinline__ int vpos(int w) {
    return ((w & 3) << 3) + ((w >> 3) << 1) + ((w >> 2) & 1);
}

// ---------------------------------------------------------------------------
// mask flag: g_mflag[b] = 1 iff mask[b][*] all nonzero
// ---------------------------------------------------------------------------
__global__ __launch_bounds__(128)
void maskflag(const int* __restrict__ mask)
{
    __shared__ int s[128];
    const int b = blockIdx.x, tid = threadIdx.x;
    int all1 = 1;
    for (int i = tid; i < L_; i += 128) all1 &= (mask[b * L_ + i] != 0);
    s[tid] = all1;
    __syncthreads();
    for (int st = 64; st; st >>= 1) {
        if (tid < st) s[tid] &= s[tid + st];
        __syncthreads();
    }
    if (tid == 0) g_mflag[b] = s[0];
}

// ---------------------------------------------------------------------------
// V prep: v [b][kv][h*32+d] f32  ->  g_vh/g_vl transposed split bf16 words
// ---------------------------------------------------------------------------
__global__ __launch_bounds__(128)
void vprep(const float* __restrict__ v)
{
    __shared__ float sv[64 * 36];
    __shared__ uint32_t swh[32 * 36], swl[32 * 36];
    const int bx = blockIdx.x;
    const int kt = bx & 31, h = (bx >> 5) & 7, b = bx >> 8;
    const int tid = threadIdx.x;
    const float* src = v + ((size_t)(b * L_ + kt * 64)) * H_ + h * 32;

    #pragma unroll
    for (int u = 0; u < 4; u++) {
        int idx = tid + u * 128;
        int row = idx >> 3, c4 = idx & 7;
        *(float4*)&sv[row * 36 + c4 * 4] = *(const float4*)&src[row * H_ + c4 * 4];
    }
    __syncthreads();
    #pragma unroll
    for (int u = 0; u < 8; u++) {
        int idx = tid + u * 128;
        int drow = idx >> 5, w = idx & 31;
        float x = sv[(2 * w) * 36 + drow];
        float y = sv[(2 * w + 1) * 36 + drow];
        uint32_t hw, lw; split2(x, y, hw, lw);
        int p = vpos(w);
        swh[drow * 36 + p] = hw;
        swl[drow * 36 + p] = lw;
    }
    __syncthreads();
    uint32_t* gh = g_vh + (size_t)bx * 1152;
    uint32_t* gl = g_vl + (size_t)bx * 1152;
    #pragma unroll
    for (int u = 0; u < 9; u++) {
        int idx = tid + u * 128;
        if (idx < 1152) { gh[idx] = swh[idx]; gl[idx] = swl[idx]; }
    }
}

// ---------------------------------------------------------------------------
// GEMM1 (fp16 2x): keff = k_b @ Wb^T + bb + k, written as fp16 K image.
// ---------------------------------------------------------------------------
#define KAH 0
#define KAL (128 * 20)
#define KWH (2 * 128 * 20)
#define GK_SMEM_WORDS (2 * 128 * 20 + 64 * 20)
#define GK_SMEM_BYTES (GK_SMEM_WORDS * 4)

__global__ __launch_bounds__(256)
void gemm_keff(const float* __restrict__ Ain,
               const float* __restrict__ W,
               const float* __restrict__ bias,
               const float* __restrict__ add)
{
    extern __shared__ uint32_t smw[];
    const int m0  = blockIdx.y * 128;
    const int n0  = blockIdx.x * 64;
    const int tid = threadIdx.x;
    const int warp   = tid >> 5;
    const int lane   = tid & 31;
    const int warp_m = warp >> 1;
    const int warp_n = warp & 1;
    const int g = lane >> 2;
    const int t = lane & 3;

    float acc[2][4][4] = {};

    float4 xa[4], xw[2];
    #pragma unroll
    for (int u = 0; u < 4; u++) {
        int idx = tid + u * 256;
        xa[u] = *(const float4*)&Ain[(size_t)(m0 + (idx >> 3)) * H_ + (idx & 7) * 4];
    }
    #pragma unroll
    for (int u = 0; u < 2; u++) {
        int idx = tid + u * 256;
        xw[u] = *(const float4*)&W[(size_t)(n0 + (idx >> 3)) * H_ + (idx & 7) * 4];
    }

    for (int k0 = 0; k0 < H_; k0 += 32) {
        #pragma unroll
        for (int u = 0; u < 4; u++) {
            int idx = tid + u * 256;
            int row = idx >> 3, c4 = idx & 7;
            uint32_t h0, l0, h1, l1;
            split2h(xa[u].x, xa[u].y, h0, l0);
            split2h(xa[u].z, xa[u].w, h1, l1);
            *(uint2*)&smw[KAH + row * 20 + c4 * 2] = make_uint2(h0, h1);
            *(uint2*)&smw[KAL + row * 20 + c4 * 2] = make_uint2(l0, l1);
        }
        #pragma unroll
        for (int u = 0; u < 2; u++) {
            int idx = tid + u * 256;
            int row = idx >> 3, c4 = idx & 7;
            uint32_t h0 = packh(xw[u].x, xw[u].y);
            uint32_t h1 = packh(xw[u].z, xw[u].w);
            *(uint2*)&smw[KWH + row * 20 + c4 * 2] = make_uint2(h0, h1);
        }
        __syncthreads();

        if (k0 + 32 < H_) {
            #pragma unroll
            for (int u = 0; u < 4; u++) {
                int idx = tid + u * 256;
                xa[u] = *(const float4*)&Ain[(size_t)(m0 + (idx >> 3)) * H_ +
                                             k0 + 32 + (idx & 7) * 4];
            }
            #pragma unroll
            for (int u = 0; u < 2; u++) {
                int idx = tid + u * 256;
                xw[u] = *(const float4*)&W[(size_t)(n0 + (idx >> 3)) * H_ +
                                           k0 + 32 + (idx & 7) * 4];
            }
        }

        #pragma unroll
        for (int s = 0; s < 2; s++) {
            uint32_t ah[2][4], al[2][4];
            #pragma unroll
            for (int mt = 0; mt < 2; mt++) {
                int r0 = (warp_m * 32 + mt * 16 + g) * 20 + 8 * s + t;
                ah[mt][0] = smw[KAH + r0];
                ah[mt][1] = smw[KAH + r0 + 160];
                ah[mt][2] = smw[KAH + r0 + 4];
                ah[mt][3] = smw[KAH + r0 + 164];
                al[mt][0] = smw[KAL + r0];
                al[mt][1] = smw[KAL + r0 + 160];
                al[mt][2] = smw[KAL + r0 + 4];
                al[mt][3] = smw[KAL + r0 + 164];
            }
            #pragma unroll
            for (int nt = 0; nt < 4; nt++) {
                int rw = (warp_n * 32 + nt * 8 + g) * 20 + 8 * s + t;
                uint32_t wh0 = smw[KWH + rw];
                uint32_t wh1 = smw[KWH + rw + 4];
                #pragma unroll
                for (int mt = 0; mt < 2; mt++) {
                    mma16h(acc[mt][nt], al[mt], wh0, wh1);
                    mma16h(acc[mt][nt], ah[mt], wh0, wh1);
                }
            }
        }
        __syncthreads();
    }

    #pragma unroll
    for (int mt = 0; mt < 2; mt++) {
        #pragma unroll
        for (int nt = 0; nt < 4; nt++) {
            int n  = n0 + warp_n * 32 + nt * 8 + 2 * t;
            int mA = m0 + warp_m * 32 + mt * 16 + g;
            int mB = mA + 8;
            float2 bs = *(const float2*)&bias[n];
            float x0 = acc[mt][nt][0] + bs.x, x1 = acc[mt][nt][1] + bs.y;
            float y0 = acc[mt][nt][2] + bs.x, y1 = acc[mt][nt][3] + bs.y;
            float2 a0 = *(const float2*)&add[(size_t)mA * H_ + n];
            float2 a1 = *(const float2*)&add[(size_t)mB * H_ + n];
            x0 += a0.x; x1 += a0.y; y0 += a1.x; y1 += a1.y;
            int h = n >> 5;
            int wd = (n & 31) >> 1;
            int p = kpos(wd);
            {
                int bi = mA >> 11, l = mA & 2047;
                size_t base = (((size_t)(bi * NH_ + h) * 32 + (l >> 6)) * 64
                               + (l & 63)) * 16 + p;
                g_kh[base] = packh(x0, x1);
            }
            {
                int bi = mB >> 11, l = mB & 2047;
                size_t base = (((size_t)(bi * NH_ + h) * 32 + (l >> 6)) * 64
                               + (l & 63)) * 16 + p;
                g_kh[base] = packh(y0, y1);
            }
        }
    }
}

// ---------------------------------------------------------------------------
// GEMM2 (bf16 3x, unchanged): out = hidden @ Ww^T + bw
// ---------------------------------------------------------------------------
#define GAH 0
#define GAL (128 * 20)
#define GWH (2 * 128 * 20)
#define GWL (2 * 128 * 20 + 64 * 20)
#define GEMM_SMEM_WORDS (2 * 128 * 20 + 2 * 64 * 20)
#define GEMM_SMEM_BYTES (GEMM_SMEM_WORDS * 4)

__global__ __launch_bounds__(256)
void gemm_out(const float* __restrict__ W,
              const float* __restrict__ bias,
              float* __restrict__ outp)
{
    extern __shared__ uint32_t smw[];
    const float* A = g_hidden;

    const int m0  = blockIdx.y * 128;
    const int n0  = blockIdx.x * 64;
    const int tid = threadIdx.x;
    const int warp   = tid >> 5;
    const int lane   = tid & 31;
    const int warp_m = warp >> 1;
    const int warp_n = warp & 1;
    const int g = lane >> 2;
    const int t = lane & 3;

    float acc[2][4][4] = {};

    float4 xa[4], xw[2];
    #pragma unroll
    for (int u = 0; u < 4; u++) {
        int idx = tid + u * 256;
        xa[u] = *(const float4*)&A[(size_t)(m0 + (idx >> 3)) * H_ + (idx & 7) * 4];
    }
    #pragma unroll
    for (int u = 0; u < 2; u++) {
        int idx = tid + u * 256;
        xw[u] = *(const float4*)&W[(size_t)(n0 + (idx >> 3)) * H_ + (idx & 7) * 4];
    }

    for (int k0 = 0; k0 < H_; k0 += 32) {
        #pragma unroll
        for (int u = 0; u < 4; u++) {
            int idx = tid + u * 256;
            int row = idx >> 3, c4 = idx & 7;
            uint32_t h0, l0, h1, l1;
            split2(xa[u].x, xa[u].y, h0, l0);
            split2(xa[u].z, xa[u].w, h1, l1);
            *(uint2*)&smw[GAH + row * 20 + c4 * 2] = make_uint2(h0, h1);
            *(uint2*)&smw[GAL + row * 20 + c4 * 2] = make_uint2(l0, l1);
        }
        #pragma unroll
        for (int u = 0; u < 2; u++) {
            int idx = tid + u * 256;
            int row = idx >> 3, c4 = idx & 7;
            uint32_t h0, l0, h1, l1;
            split2(xw[u].x, xw[u].y, h0, l0);
            split2(xw[u].z, xw[u].w, h1, l1);
            *(uint2*)&smw[GWH + row * 20 + c4 * 2] = make_uint2(h0, h1);
            *(uint2*)&smw[GWL + row * 20 + c4 * 2] = make_uint2(l0, l1);
        }
        __syncthreads();

        if (k0 + 32 < H_) {
            #pragma unroll
            for (int u = 0; u < 4; u++) {
                int idx = tid + u * 256;
                xa[u] = *(const float4*)&A[(size_t)(m0 + (idx >> 3)) * H_ +
                                           k0 + 32 + (idx & 7) * 4];
            }
            #pragma unroll
            for (int u = 0; u < 2; u++) {
                int idx = tid + u * 256;
                xw[u] = *(const float4*)&W[(size_t)(n0 + (idx >> 3)) * H_ +
                                           k0 + 32 + (idx & 7) * 4];
            }
        }

        #pragma unroll
        for (int s = 0; s < 2; s++) {
            uint32_t ah[2][4], al[2][4];
            #pragma unroll
            for (int mt = 0; mt < 2; mt++) {
                int r0 = (warp_m * 32 + mt * 16 + g) * 20 + 8 * s + t;
                ah[mt][0] = smw[GAH + r0];
                ah[mt][1] = smw[GAH + r0 + 160];
                ah[mt][2] = smw[GAH + r0 + 4];
                ah[mt][3] = smw[GAH + r0 + 164];
                al[mt][0] = smw[GAL + r0];
                al[mt][1] = smw[GAL + r0 + 160];
                al[mt][2] = smw[GAL + r0 + 4];
                al[mt][3] = smw[GAL + r0 + 164];
            }
            #pragma unroll
            for (int nt = 0; nt < 4; nt++) {
                int rw = (warp_n * 32 + nt * 8 + g) * 20 + 8 * s + t;
                uint32_t wh0 = smw[GWH + rw];
                uint32_t wh1 = smw[GWH + rw + 4];
                uint32_t wl0 = smw[GWL + rw];
                uint32_t wl1 = smw[GWL + rw + 4];
                #pragma unroll
                for (int mt = 0; mt < 2; mt++) {
                    mma16(acc[mt][nt], al[mt], wh0, wh1);
                    mma16(acc[mt][nt], ah[mt], wl0, wl1);
                    mma16(acc[mt][nt], ah[mt], wh0, wh1);
                }
            }
        }
        __syncthreads();
    }

    #pragma unroll
    for (int mt = 0; mt < 2; mt++) {
        #pragma unroll
        for (int nt = 0; nt < 4; nt++) {
            int n  = n0 + warp_n * 32 + nt * 8 + 2 * t;
            int mA = m0 + warp_m * 32 + mt * 16 + g;
            int mB = mA + 8;
            float2 bs = *(const float2*)&bias[n];
            *(float2*)&outp[(size_t)mA * H_ + n] =
                make_float2(acc[mt][nt][0] + bs.x, acc[mt][nt][1] + bs.y);
            *(float2*)&outp[(size_t)mB * H_ + n] =
                make_float2(acc[mt][nt][2] + bs.x, acc[mt][nt][3] + bs.y);
        }
    }
}

// ---------------------------------------------------------------------------
// Flash attention: S in fp16 (Q 2x-split, K single fp16), PV in bf16x3,
// static softmax (exp2 domain), P in registers.
// PHASE-STAGGERED body: S_h0 -> exp_h0 -> S_h1 -> PV_h0 -> exp_h1 -> PV_h1
// keeps independent HMMA adjacent to every MUFU block so the tensor pipe
// never drains while all warps sit in the exp phase (the measured 25% idle).
// ---------------------------------------------------------------------------
#define OKH 0
#define OVH 1024
#define OVL 2176
#define OMS 3328
#define BUFSZ 3392
#define ATTN_SMEM_WORDS (2 * BUFSZ)
#define ATTN_SMEM_BYTES (ATTN_SMEM_WORDS * 4)

__device__ __forceinline__ void fill_tile(uint32_t sbase, int bufbase,
                                          int bh, int kt,
                                          const int* __restrict__ maskb)
{
    const int tid = threadIdx.x;
    size_t kb = ((size_t)bh * 32 + kt) * 1024;
    size_t vb = ((size_t)bh * 32 + kt) * 1152;
    const uint32_t* gkh = g_kh + kb;
    const uint32_t* gvh = g_vh + vb;
    const uint32_t* gvl = g_vl + vb;
    {   // K: 1024 words = 256 cp16; one per thread
        int i = tid * 4;
        cp16(sbase + (bufbase + OKH) * 4 + i * 4, gkh + i);
    }
    #pragma unroll
    for (int u = 0; u < 2; u++) {
        int i = tid + u * 256;
        if (i < 288) {
            cp16(sbase + (bufbase + OVH + i * 4) * 4, gvh + i * 4);
            cp16(sbase + (bufbase + OVL + i * 4) * 4, gvl + i * 4);
        }
    }
    if (tid < 16)
        cp16(sbase + (bufbase + OMS + tid * 4) * 4, maskb + kt * 64 + tid * 4);
    cp_commit();
}

__global__ __launch_bounds__(256)
void attn_tc(const float* __restrict__ q,
             const int*   __restrict__ mask,
             const float* __restrict__ scale_w)
{
    extern __shared__ uint32_t smu[];
    const uint32_t sbase = (uint32_t)__cvta_generic_to_shared(smu);

    const int b   = blockIdx.z;
    const int h   = blockIdx.y;
    const int q0  = blockIdx.x * 128;
    const int bh  = b * NH_ + h;
    const int tid = threadIdx.x;
    const int warp = tid >> 5;
    const int lane = tid & 31;
    const int g = lane >> 2;
    const int t = lane & 3;
    // exp2-domain: fold log2e into the Q pre-scale; p = exp2(s')
    const float rs = 0.17677669529663687f * 1.4426950408889634f;

    const int r0l = warp * 16 + g;
    const int r1l = r0l + 8;
    const int* maskb = mask + b * L_;
    const int noMask = g_mflag[b];

    // ---- Q fragments: 2 k16-steps, split fp16 (22-bit Q) ----
    const float s0 = scale_w[h * L_ + q0 + r0l] * rs;
    const float s1 = scale_w[h * L_ + q0 + r1l] * rs;
    const float* qb = q + (size_t)(b * L_ + q0) * H_ + h * DH_;

    uint32_t qh2[2][4], ql2[2][4];
    #pragma unroll
    for (int s = 0; s < 2; s++) {
        float2 v0 = *(const float2*)&qb[r0l * H_ + s * 16 + 2 * t];
        float2 v2 = *(const float2*)&qb[r0l * H_ + s * 16 + 2 * t + 8];
        float2 v1 = *(const float2*)&qb[r1l * H_ + s * 16 + 2 * t];
        float2 v3 = *(const float2*)&qb[r1l * H_ + s * 16 + 2 * t + 8];
        split2h(v0.x * s0, v0.y * s0, qh2[s][0], ql2[s][0]);
        split2h(v1.x * s1, v1.y * s1, qh2[s][1], ql2[s][1]);
        split2h(v2.x * s0, v2.y * s0, qh2[s][2], ql2[s][2]);
        split2h(v3.x * s1, v3.y * s1, qh2[s][3], ql2[s][3]);
    }

    float l0 = 0.f, l1 = 0.f;
    float o[4][4] = {};

    const int koff = g * 16 + t * 4;
    const int voff = g * 36 + t * 8;

    fill_tile(sbase, 0, bh, 0, maskb);

    for (int kt = 0; kt < 32; kt++) {
        const int buf = (kt & 1) ? BUFSZ : 0;
        cp_wait0();
        __syncthreads();
        if (kt + 1 < 32)
            fill_tile(sbase, (kt & 1) ? 0 : BUFSZ, bh, kt + 1, maskb);

        const uint32_t* KH = smu + buf + OKH;
        const uint32_t* VH = smu + buf + OVH;
        const uint32_t* VL = smu + buf + OVL;
        const int*      MS = (const int*)(smu + buf + OMS);

        // ======== S half0 ========
        float c0[4][4] = {};
        #pragma unroll
        for (int jj = 0; jj < 4; jj++) {
            uint4 bhw = *(const uint4*)(KH + jj * 128 + koff);
            mma16h(c0[jj], qh2[0], bhw.x, bhw.y);
            mma16h(c0[jj], qh2[1], bhw.z, bhw.w);
            mma16h(c0[jj], ql2[0], bhw.x, bhw.y);
            mma16h(c0[jj], ql2[1], bhw.z, bhw.w);
        }
        if (!noMask) {
            #pragma unroll
            for (int jj = 0; jj < 4; jj++) {
                int2 mv = *(const int2*)(MS + jj * 8 + 2 * t);
                if (mv.x == 0) { c0[jj][0] = -1e9f; c0[jj][2] = -1e9f; }
                if (mv.y == 0) { c0[jj][1] = -1e9f; c0[jj][3] = -1e9f; }
            }
        }
        // ======== exp/pack half0 -> AP0 ========
        uint32_t APH0[2][4], APL0[2][4];
        #pragma unroll
        for (int kb2 = 0; kb2 < 2; kb2++) {
            float pA0 = ex2f(c0[2*kb2][0]);
            float pA1 = ex2f(c0[2*kb2][1]);
            float pA2 = ex2f(c0[2*kb2][2]);
            float pA3 = ex2f(c0[2*kb2][3]);
            float pB0 = ex2f(c0[2*kb2+1][0]);
            float pB1 = ex2f(c0[2*kb2+1][1]);
            float pB2 = ex2f(c0[2*kb2+1][2]);
            float pB3 = ex2f(c0[2*kb2+1][3]);
            l0 += pA0 + pA1 + pB0 + pB1;
            l1 += pA2 + pA3 + pB2 + pB3;
            split2(pA0, pA1, APH0[kb2][0], APL0[kb2][0]);
            split2(pA2, pA3, APH0[kb2][1], APL0[kb2][1]);
            split2(pB0, pB1, APH0[kb2][2], APL0[kb2][2]);
            split2(pB2, pB3, APH0[kb2][3], APL0[kb2][3]);
        }
        // ======== S half1 (tensor work adjacent to exp blocks) ========
        float c1[4][4] = {};
        #pragma unroll
        for (int jj = 0; jj < 4; jj++) {
            uint4 bhw = *(const uint4*)(KH + (jj + 4) * 128 + koff);
            mma16h(c1[jj], qh2[0], bhw.x, bhw.y);
            mma16h(c1[jj], qh2[1], bhw.z, bhw.w);
            mma16h(c1[jj], ql2[0], bhw.x, bhw.y);
            mma16h(c1[jj], ql2[1], bhw.z, bhw.w);
        }
        // ======== PV half0 (independent of c1; overlaps exp_h1 below) ====
        #pragma unroll
        for (int nb = 0; nb < 4; nb++) {
            uint4 vh = *(const uint4*)(VH + nb * 288 + voff);
            uint4 vl = *(const uint4*)(VL + nb * 288 + voff);
            mma16(o[nb], APH0[0], vh.x, vh.y);
            mma16(o[nb], APH0[1], vh.z, vh.w);
            mma16(o[nb], APL0[0], vh.x, vh.y);
            mma16(o[nb], APL0[1], vh.z, vh.w);
            mma16(o[nb], APH0[0], vl.x, vl.y);
            mma16(o[nb], APH0[1], vl.z, vl.w);
        }
        // ======== mask + exp/pack half1 ========
        if (!noMask) {
            #pragma unroll
            for (int jj = 0; jj < 4; jj++) {
                int2 mv = *(const int2*)(MS + (jj + 4) * 8 + 2 * t);
                if (mv.x == 0) { c1[jj][0] = -1e9f; c1[jj][2] = -1e9f; }
                if (mv.y == 0) { c1[jj][1] = -1e9f; c1[jj][3] = -1e9f; }
            }
        }
        uint32_t APH1[2][4], APL1[2][4];
        #pragma unroll
        for (int kb2 = 0; kb2 < 2; kb2++) {
            float pA0 = ex2f(c1[2*kb2][0]);
            float pA1 = ex2f(c1[2*kb2][1]);
            float pA2 = ex2f(c1[2*kb2][2]);
            float pA3 = ex2f(c1[2*kb2][3]);
            float pB0 = ex2f(c1[2*kb2+1][0]);
            float pB1 = ex2f(c1[2*kb2+1][1]);
            float pB2 = ex2f(c1[2*kb2+1][2]);
            float pB3 = ex2f(c1[2*kb2+1][3]);
            l0 += pA0 + pA1 + pB0 + pB1;
            l1 += pA2 + pA3 + pB2 + pB3;
            split2(pA0, pA1, APH1[kb2][0], APL1[kb2][0]);
            split2(pA2, pA3, APH1[kb2][1], APL1[kb2][1]);
            split2(pB0, pB1, APH1[kb2][2], APL1[kb2][2]);
            split2(pB2, pB3, APH1[kb2][3], APL1[kb2][3]);
        }
        // ======== PV half1 ========
        #pragma unroll
        for (int nb = 0; nb < 4; nb++) {
            uint4 vh = *(const uint4*)(VH + nb * 288 + voff + 4);
            uint4 vl = *(const uint4*)(VL + nb * 288 + voff + 4);
            mma16(o[nb], APH1[0], vh.x, vh.y);
            mma16(o[nb], APH1[1], vh.z, vh.w);
            mma16(o[nb], APL1[0], vh.x, vh.y);
            mma16(o[nb], APL1[1], vh.z, vh.w);
            mma16(o[nb], APH1[0], vl.x, vl.y);
            mma16(o[nb], APH1[1], vl.z, vl.w);
        }
    }

    // ---- one-time l reduction across the 4-lane groups ----
    l0 += __shfl_xor_sync(0xffffffffu, l0, 1);
    l0 += __shfl_xor_sync(0xffffffffu, l0, 2);
    l1 += __shfl_xor_sync(0xffffffffu, l1, 1);
    l1 += __shfl_xor_sync(0xffffffffu, l1, 2);

    // ---- normalize + store (fused head transpose) ----
    float inv0 = 1.f / l0, inv1 = 1.f / l1;
    #pragma unroll
    for (int nb = 0; nb < 4; nb++) {
        int col = h * DH_ + nb * 8 + 2 * t;
        float2 w0 = make_float2(o[nb][0] * inv0, o[nb][1] * inv0);
        float2 w1 = make_float2(o[nb][2] * inv1, o[nb][3] * inv1);
        *(float2*)&g_hidden[(size_t)(b * L_ + q0 + r0l) * H_ + col] = w0;
        *(float2*)&g_hidden[(size_t)(b * L_ + q0 + r1l) * H_ + col] = w1;
    }
}

// ---------------------------------------------------------------------------
// Launch. Inputs: 0=q 1=k 2=v 3=k_b 4=mask 5=scale_w 6=Wb 7=bb 8=Ww 9=bw
// ---------------------------------------------------------------------------
extern "C" void kernel_launch(void* const* d_in, const int* in_sizes, int n_in,
                              void* d_out, int out_size)
{
    const float* q       = (const float*)d_in[0];
    const float* k       = (const float*)d_in[1];
    const float* v       = (const float*)d_in[2];
    const float* k_b     = (const float*)d_in[3];
    const int*   mask    = (const int*)  d_in[4];
    const float* scale_w = (const float*)d_in[5];
    const float* Wb      = (const float*)d_in[6];
    const float* bb      = (const float*)d_in[7];
    const float* Ww      = (const float*)d_in[8];
    const float* bw      = (const float*)d_in[9];
    float* out = (float*)d_out;

    cudaFuncSetAttribute(attn_tc, cudaFuncAttributeMaxDynamicSharedMemorySize,
                         ATTN_SMEM_BYTES);
    cudaFuncSetAttribute(gemm_keff,
                         cudaFuncAttributeMaxDynamicSharedMemorySize, GK_SMEM_BYTES);
    cudaFuncSetAttribute(gemm_out,
                         cudaFuncAttributeMaxDynamicSharedMemorySize, GEMM_SMEM_BYTES);

    // mask all-ones flags + V split/transpose prep
    maskflag<<<B_, 128>>>(mask);
    vprep<<<B_ * NH_ * 32, 128>>>(v);

    // keff = k_b @ Wb^T + bb + k   (written directly as fp16 K image)
    gemm_keff<<<dim3(H_ / 64, M_ / 128), 256, GK_SMEM_BYTES>>>(k_b, Wb, bb, k);

    // hidden = attention(q, keff, v)
    attn_tc<<<dim3(L_ / 128, NH_, B_), 256, ATTN_SMEM_BYTES>>>(q, mask, scale_w);

    // out = hidden @ Ww^T + bw
    gemm_out<<<dim3(H_ / 64, M_ / 128), 256, GEMM_SMEM_BYTES>>>(Ww, bw, out);
}

// round 15
// speedup vs baseline: 1.2768x; 1.0456x over previous
#include <cuda_runtime.h>
#include <cuda_fp16.h>
#include <cstdint>

#define B_  4
#define L_  2048
#define H_  256
#define NH_ 8
#define DH_ 32
#define M_  (B_*L_)   // 8192 rows

// ---------------------------------------------------------------------------
// Global scratch (allocation-free rule: __device__ globals)
// K(eff) fp16 words (single, unsplit), [b][h][tile64][key64][16 words]
// V^T split bf16 words, [b][h][tile64][drow32][36 words] (32 used)
// ---------------------------------------------------------------------------
__device__ __align__(16) uint32_t g_kh[B_*NH_*32*64*16];
__device__ __align__(16) uint32_t g_vh[B_*NH_*32*32*36];
__device__ __align__(16) uint32_t g_vl[B_*NH_*32*32*36];
__device__ __align__(16) float    g_hidden[M_ * H_];
__device__ int g_mflag[B_];   // 1 = no masked keys in this batch row

// ---------------------------------------------------------------------------
// helpers
// ---------------------------------------------------------------------------
__device__ __forceinline__ float ex2f(float x) {
    float r; asm("ex2.approx.f32 %0, %1;" : "=f"(r) : "f"(x)); return r;
}
// bf16 mma (PV + output GEMM)
__device__ __forceinline__ void mma16(float c[4], const uint32_t a[4],
                                      uint32_t b0, uint32_t b1) {
    asm("mma.sync.aligned.m16n8k16.row.col.f32.bf16.bf16.f32 "
        "{%0,%1,%2,%3},{%4,%5,%6,%7},{%8,%9},{%0,%1,%2,%3};"
        : "+f"(c[0]), "+f"(c[1]), "+f"(c[2]), "+f"(c[3])
        : "r"(a[0]), "r"(a[1]), "r"(a[2]), "r"(a[3]), "r"(b0), "r"(b1));
}
// fp16 mma (S + keff GEMM)
__device__ __forceinline__ void mma16h(float c[4], const uint32_t a[4],
                                       uint32_t b0, uint32_t b1) {
    asm("mma.sync.aligned.m16n8k16.row.col.f32.f16.f16.f32 "
        "{%0,%1,%2,%3},{%4,%5,%6,%7},{%8,%9},{%0,%1,%2,%3};"
        : "+f"(c[0]), "+f"(c[1]), "+f"(c[2]), "+f"(c[3])
        : "r"(a[0]), "r"(a[1]), "r"(a[2]), "r"(a[3]), "r"(b0), "r"(b1));
}
// bf16 pack/split
__device__ __forceinline__ uint32_t packbf(float x, float y) {
    uint32_t r; asm("cvt.rn.bf16x2.f32 %0, %1, %2;" : "=r"(r) : "f"(y), "f"(x));
    return r;
}
__device__ __forceinline__ void split2(float x, float y,
                                       uint32_t& hw, uint32_t& lw) {
    hw = packbf(x, y);
    float xh = __uint_as_float(hw << 16);
    float yh = __uint_as_float(hw & 0xffff0000u);
    lw = packbf(x - xh, y - yh);
}
// fp16 pack/split
__device__ __forceinline__ uint32_t packh(float x, float y) {
    uint32_t r; asm("cvt.rn.f16x2.f32 %0, %1, %2;" : "=r"(r) : "f"(y), "f"(x));
    return r;
}
__device__ __forceinline__ void split2h(float x, float y,
                                        uint32_t& hw, uint32_t& lw) {
    hw = packh(x, y);
    __half2 h2 = *reinterpret_cast<__half2*>(&hw);
    float xh = __half2float(__low2half(h2));
    float yh = __half2float(__high2half(h2));
    lw = packh(x - xh, y - yh);
}
__device__ __forceinline__ void cp16(uint32_t saddr, const void* gaddr) {
    asm volatile("cp.async.cg.shared.global [%0], [%1], 16;"
                 :: "r"(saddr), "l"(gaddr));
}
__device__ __forceinline__ void cp_commit() {
    asm volatile("cp.async.commit_group;");
}
__device__ __forceinline__ void cp_wait0() {
    asm volatile("cp.async.wait_group 0;" ::: "memory");
}

// word-position permutations: u = w&7, s = w>>3
// K rows have 16 words: pos = (u&3)*4 + 2s + (u>>2)
// V rows have 32 words: pos = (u&3)*8 + 2s + (u>>2)
__device__ __forceinline__ int kpos(int w) {
    return ((w & 3) << 2) + ((w >> 3) << 1) + ((w >> 2) & 1);
}
__device__ __forceinline__ int vpos(int w) {
    return ((w & 3) << 3) + ((w >> 3) << 1) + ((w >> 2) & 1);
}

// ---------------------------------------------------------------------------
// mask flag: g_mflag[b] = 1 iff mask[b][*] all nonzero
// ---------------------------------------------------------------------------
__global__ __launch_bounds__(128)
void maskflag(const int* __restrict__ mask)
{
    __shared__ int s[128];
    const int b = blockIdx.x, tid = threadIdx.x;
    int all1 = 1;
    for (int i = tid; i < L_; i += 128) all1 &= (mask[b * L_ + i] != 0);
    s[tid] = all1;
    __syncthreads();
    for (int st = 64; st; st >>= 1) {
        if (tid < st) s[tid] &= s[tid + st];
        __syncthreads();
    }
    if (tid == 0) g_mflag[b] = s[0];
}

// ---------------------------------------------------------------------------
// V prep: v [b][kv][h*32+d] f32  ->  g_vh/g_vl transposed split bf16 words
// ---------------------------------------------------------------------------
__global__ __launch_bounds__(128)
void vprep(const float* __restrict__ v)
{
    __shared__ float sv[64 * 36];
    __shared__ uint32_t swh[32 * 36], swl[32 * 36];
    const int bx = blockIdx.x;
    const int kt = bx & 31, h = (bx >> 5) & 7, b = bx >> 8;
    const int tid = threadIdx.x;
    const float* src = v + ((size_t)(b * L_ + kt * 64)) * H_ + h * 32;

    #pragma unroll
    for (int u = 0; u < 4; u++) {
        int idx = tid + u * 128;
        int row = idx >> 3, c4 = idx & 7;
        *(float4*)&sv[row * 36 + c4 * 4] = *(const float4*)&src[row * H_ + c4 * 4];
    }
    __syncthreads();
    #pragma unroll
    for (int u = 0; u < 8; u++) {
        int idx = tid + u * 128;
        int drow = idx >> 5, w = idx & 31;
        float x = sv[(2 * w) * 36 + drow];
        float y = sv[(2 * w + 1) * 36 + drow];
        uint32_t hw, lw; split2(x, y, hw, lw);
        int p = vpos(w);
        swh[drow * 36 + p] = hw;
        swl[drow * 36 + p] = lw;
    }
    __syncthreads();
    uint32_t* gh = g_vh + (size_t)bx * 1152;
    uint32_t* gl = g_vl + (size_t)bx * 1152;
    #pragma unroll
    for (int u = 0; u < 9; u++) {
        int idx = tid + u * 128;
        if (idx < 1152) { gh[idx] = swh[idx]; gl[idx] = swl[idx]; }
    }
}

// ---------------------------------------------------------------------------
// GEMM1 (fp16 2x, double-buffered smem, ONE sync/iter):
// keff = k_b @ Wb^T + bb + k, written as fp16 K image.
// ---------------------------------------------------------------------------
#define KAH 0
#define KAL (128 * 20)
#define KWH (2 * 128 * 20)
#define KBUF (2 * 128 * 20 + 64 * 20)      // 6400 words per buffer
#define GK_SMEM_WORDS (2 * KBUF)
#define GK_SMEM_BYTES (GK_SMEM_WORDS * 4)

__global__ __launch_bounds__(256)
void gemm_keff(const float* __restrict__ Ain,
               const float* __restrict__ W,
               const float* __restrict__ bias,
               const float* __restrict__ add)
{
    extern __shared__ uint32_t smw[];
    const int m0  = blockIdx.y * 128;
    const int n0  = blockIdx.x * 64;
    const int tid = threadIdx.x;
    const int warp   = tid >> 5;
    const int lane   = tid & 31;
    const int warp_m = warp >> 1;
    const int warp_n = warp & 1;
    const int g = lane >> 2;
    const int t = lane & 3;

    float acc[2][4][4] = {};

    float4 xa[4], xw[2];
    #pragma unroll
    for (int u = 0; u < 4; u++) {
        int idx = tid + u * 256;
        xa[u] = *(const float4*)&Ain[(size_t)(m0 + (idx >> 3)) * H_ + (idx & 7) * 4];
    }
    #pragma unroll
    for (int u = 0; u < 2; u++) {
        int idx = tid + u * 256;
        xw[u] = *(const float4*)&W[(size_t)(n0 + (idx >> 3)) * H_ + (idx & 7) * 4];
    }

    for (int k0 = 0; k0 < H_; k0 += 32) {
        const int bb = ((k0 >> 5) & 1) ? KBUF : 0;
        #pragma unroll
        for (int u = 0; u < 4; u++) {
            int idx = tid + u * 256;
            int row = idx >> 3, c4 = idx & 7;
            uint32_t h0, l0, h1, l1;
            split2h(xa[u].x, xa[u].y, h0, l0);
            split2h(xa[u].z, xa[u].w, h1, l1);
            *(uint2*)&smw[bb + KAH + row * 20 + c4 * 2] = make_uint2(h0, h1);
            *(uint2*)&smw[bb + KAL + row * 20 + c4 * 2] = make_uint2(l0, l1);
        }
        #pragma unroll
        for (int u = 0; u < 2; u++) {
            int idx = tid + u * 256;
            int row = idx >> 3, c4 = idx & 7;
            uint32_t h0 = packh(xw[u].x, xw[u].y);
            uint32_t h1 = packh(xw[u].z, xw[u].w);
            *(uint2*)&smw[bb + KWH + row * 20 + c4 * 2] = make_uint2(h0, h1);
        }
        __syncthreads();

        if (k0 + 32 < H_) {
            #pragma unroll
            for (int u = 0; u < 4; u++) {
                int idx = tid + u * 256;
                xa[u] = *(const float4*)&Ain[(size_t)(m0 + (idx >> 3)) * H_ +
                                             k0 + 32 + (idx & 7) * 4];
            }
            #pragma unroll
            for (int u = 0; u < 2; u++) {
                int idx = tid + u * 256;
                xw[u] = *(const float4*)&W[(size_t)(n0 + (idx >> 3)) * H_ +
                                           k0 + 32 + (idx & 7) * 4];
            }
        }

        #pragma unroll
        for (int s = 0; s < 2; s++) {
            uint32_t ah[2][4], al[2][4];
            #pragma unroll
            for (int mt = 0; mt < 2; mt++) {
                int r0 = bb + (warp_m * 32 + mt * 16 + g) * 20 + 8 * s + t;
                ah[mt][0] = smw[KAH + r0];
                ah[mt][1] = smw[KAH + r0 + 160];
                ah[mt][2] = smw[KAH + r0 + 4];
                ah[mt][3] = smw[KAH + r0 + 164];
                al[mt][0] = smw[KAL + r0];
                al[mt][1] = smw[KAL + r0 + 160];
                al[mt][2] = smw[KAL + r0 + 4];
                al[mt][3] = smw[KAL + r0 + 164];
            }
            #pragma unroll
            for (int nt = 0; nt < 4; nt++) {
                int rw = bb + (warp_n * 32 + nt * 8 + g) * 20 + 8 * s + t;
                uint32_t wh0 = smw[KWH + rw];
                uint32_t wh1 = smw[KWH + rw + 4];
                #pragma unroll
                for (int mt = 0; mt < 2; mt++) {
                    mma16h(acc[mt][nt], al[mt], wh0, wh1);
                    mma16h(acc[mt][nt], ah[mt], wh0, wh1);
                }
            }
        }
        // no trailing sync: next iter writes the other buffer; buffer reuse
        // is gated by the next iteration's single sync (see analysis).
    }

    #pragma unroll
    for (int mt = 0; mt < 2; mt++) {
        #pragma unroll
        for (int nt = 0; nt < 4; nt++) {
            int n  = n0 + warp_n * 32 + nt * 8 + 2 * t;
            int mA = m0 + warp_m * 32 + mt * 16 + g;
            int mB = mA + 8;
            float2 bs = *(const float2*)&bias[n];
            float x0 = acc[mt][nt][0] + bs.x, x1 = acc[mt][nt][1] + bs.y;
            float y0 = acc[mt][nt][2] + bs.x, y1 = acc[mt][nt][3] + bs.y;
            float2 a0 = *(const float2*)&add[(size_t)mA * H_ + n];
            float2 a1 = *(const float2*)&add[(size_t)mB * H_ + n];
            x0 += a0.x; x1 += a0.y; y0 += a1.x; y1 += a1.y;
            int h = n >> 5;
            int wd = (n & 31) >> 1;
            int p = kpos(wd);
            {
                int bi = mA >> 11, l = mA & 2047;
                size_t base = (((size_t)(bi * NH_ + h) * 32 + (l >> 6)) * 64
                               + (l & 63)) * 16 + p;
                g_kh[base] = packh(x0, x1);
            }
            {
                int bi = mB >> 11, l = mB & 2047;
                size_t base = (((size_t)(bi * NH_ + h) * 32 + (l >> 6)) * 64
                               + (l & 63)) * 16 + p;
                g_kh[base] = packh(y0, y1);
            }
        }
    }
}

// ---------------------------------------------------------------------------
// GEMM2 (bf16 3x, double-buffered smem, ONE sync/iter): out = hidden@Ww^T + bw
// ---------------------------------------------------------------------------
#define GAH 0
#define GAL (128 * 20)
#define GWH (2 * 128 * 20)
#define GWL (2 * 128 * 20 + 64 * 20)
#define GBUF (2 * 128 * 20 + 2 * 64 * 20)   // 7680 words per buffer
#define GEMM_SMEM_WORDS (2 * GBUF)
#define GEMM_SMEM_BYTES (GEMM_SMEM_WORDS * 4)

__global__ __launch_bounds__(256)
void gemm_out(const float* __restrict__ W,
              const float* __restrict__ bias,
              float* __restrict__ outp)
{
    extern __shared__ uint32_t smw[];
    const float* A = g_hidden;

    const int m0  = blockIdx.y * 128;
    const int n0  = blockIdx.x * 64;
    const int tid = threadIdx.x;
    const int warp   = tid >> 5;
    const int lane   = tid & 31;
    const int warp_m = warp >> 1;
    const int warp_n = warp & 1;
    const int g = lane >> 2;
    const int t = lane & 3;

    float acc[2][4][4] = {};

    float4 xa[4], xw[2];
    #pragma unroll
    for (int u = 0; u < 4; u++) {
        int idx = tid + u * 256;
        xa[u] = *(const float4*)&A[(size_t)(m0 + (idx >> 3)) * H_ + (idx & 7) * 4];
    }
    #pragma unroll
    for (int u = 0; u < 2; u++) {
        int idx = tid + u * 256;
        xw[u] = *(const float4*)&W[(size_t)(n0 + (idx >> 3)) * H_ + (idx & 7) * 4];
    }

    for (int k0 = 0; k0 < H_; k0 += 32) {
        const int bb = ((k0 >> 5) & 1) ? GBUF : 0;
        #pragma unroll
        for (int u = 0; u < 4; u++) {
            int idx = tid + u * 256;
            int row = idx >> 3, c4 = idx & 7;
            uint32_t h0, l0, h1, l1;
            split2(xa[u].x, xa[u].y, h0, l0);
            split2(xa[u].z, xa[u].w, h1, l1);
            *(uint2*)&smw[bb + GAH + row * 20 + c4 * 2] = make_uint2(h0, h1);
            *(uint2*)&smw[bb + GAL + row * 20 + c4 * 2] = make_uint2(l0, l1);
        }
        #pragma unroll
        for (int u = 0; u < 2; u++) {
            int idx = tid + u * 256;
            int row = idx >> 3, c4 = idx & 7;
            uint32_t h0, l0, h1, l1;
            split2(xw[u].x, xw[u].y, h0, l0);
            split2(xw[u].z, xw[u].w, h1, l1);
            *(uint2*)&smw[bb + GWH + row * 20 + c4 * 2] = make_uint2(h0, h1);
            *(uint2*)&smw[bb + GWL + row * 20 + c4 * 2] = make_uint2(l0, l1);
        }
        __syncthreads();

        if (k0 + 32 < H_) {
            #pragma unroll
            for (int u = 0; u < 4; u++) {
                int idx = tid + u * 256;
                xa[u] = *(const float4*)&A[(size_t)(m0 + (idx >> 3)) * H_ +
                                           k0 + 32 + (idx & 7) * 4];
            }
            #pragma unroll
            for (int u = 0; u < 2; u++) {
                int idx = tid + u * 256;
                xw[u] = *(const float4*)&W[(size_t)(n0 + (idx >> 3)) * H_ +
                                           k0 + 32 + (idx & 7) * 4];
            }
        }

        #pragma unroll
        for (int s = 0; s < 2; s++) {
            uint32_t ah[2][4], al[2][4];
            #pragma unroll
            for (int mt = 0; mt < 2; mt++) {
                int r0 = bb + (warp_m * 32 + mt * 16 + g) * 20 + 8 * s + t;
                ah[mt][0] = smw[GAH + r0];
                ah[mt][1] = smw[GAH + r0 + 160];
                ah[mt][2] = smw[GAH + r0 + 4];
                ah[mt][3] = smw[GAH + r0 + 164];
                al[mt][0] = smw[GAL + r0];
                al[mt][1] = smw[GAL + r0 + 160];
                al[mt][2] = smw[GAL + r0 + 4];
                al[mt][3] = smw[GAL + r0 + 164];
            }
            #pragma unroll
            for (int nt = 0; nt < 4; nt++) {
                int rw = bb + (warp_n * 32 + nt * 8 + g) * 20 + 8 * s + t;
                uint32_t wh0 = smw[GWH + rw];
                uint32_t wh1 = smw[GWH + rw + 4];
                uint32_t wl0 = smw[GWL + rw];
                uint32_t wl1 = smw[GWL + rw + 4];
                #pragma unroll
                for (int mt = 0; mt < 2; mt++) {
                    mma16(acc[mt][nt], al[mt], wh0, wh1);
                    mma16(acc[mt][nt], ah[mt], wl0, wl1);
                    mma16(acc[mt][nt], ah[mt], wh0, wh1);
                }
            }
        }
    }

    #pragma unroll
    for (int mt = 0; mt < 2; mt++) {
        #pragma unroll
        for (int nt = 0; nt < 4; nt++) {
            int n  = n0 + warp_n * 32 + nt * 8 + 2 * t;
            int mA = m0 + warp_m * 32 + mt * 16 + g;
            int mB = mA + 8;
            float2 bs = *(const float2*)&bias[n];
            *(float2*)&outp[(size_t)mA * H_ + n] =
                make_float2(acc[mt][nt][0] + bs.x, acc[mt][nt][1] + bs.y);
            *(float2*)&outp[(size_t)mB * H_ + n] =
                make_float2(acc[mt][nt][2] + bs.x, acc[mt][nt][3] + bs.y);
        }
    }
}

// ---------------------------------------------------------------------------
// Flash attention: S fp16 (Q split, K single), PV bf16x3, static exp2 softmax,
// P in registers. BK=128: two 64-key subtiles per barrier/fill cycle, halving
// the per-tile cp_wait/sync/fill overhead (16 iters instead of 32).
// smem words/buffer: KH 2048 | VH 2304 | VL 2304 | MS 128 = 6784.
// ---------------------------------------------------------------------------
#define OKH 0
#define OVH 2048
#define OVL 4352
#define OMS 6656
#define BUFSZ 6784
#define ATTN_SMEM_WORDS (2 * BUFSZ)
#define ATTN_SMEM_BYTES (ATTN_SMEM_WORDS * 4)

__device__ __forceinline__ void fill_tile(uint32_t sbase, int bufbase,
                                          int bh, int kt,
                                          const int* __restrict__ maskb)
{
    const int tid = threadIdx.x;
    const uint32_t* gkh = g_kh + (size_t)bh * 32768 + (size_t)kt * 2048;
    const uint32_t* gvh = g_vh + (size_t)bh * 36864 + (size_t)kt * 2304;
    const uint32_t* gvl = g_vl + (size_t)bh * 36864 + (size_t)kt * 2304;
    #pragma unroll
    for (int u = 0; u < 2; u++) {
        int i = (tid + u * 256) * 4;          // 0..2044
        cp16(sbase + (bufbase + OKH) * 4 + i * 4, gkh + i);
    }
    #pragma unroll
    for (int u = 0; u < 3; u++) {
        int i = tid + u * 256;
        if (i < 576) {
            cp16(sbase + (bufbase + OVH + i * 4) * 4, gvh + i * 4);
            cp16(sbase + (bufbase + OVL + i * 4) * 4, gvl + i * 4);
        }
    }
    if (tid < 32)
        cp16(sbase + (bufbase + OMS + tid * 4) * 4, maskb + kt * 128 + tid * 4);
    cp_commit();
}

__global__ __launch_bounds__(256)
void attn_tc(const float* __restrict__ q,
             const int*   __restrict__ mask,
             const float* __restrict__ scale_w)
{
    extern __shared__ uint32_t smu[];
    const uint32_t sbase = (uint32_t)__cvta_generic_to_shared(smu);

    const int b   = blockIdx.z;
    const int h   = blockIdx.y;
    const int q0  = blockIdx.x * 128;
    const int bh  = b * NH_ + h;
    const int tid = threadIdx.x;
    const int warp = tid >> 5;
    const int lane = tid & 31;
    const int g = lane >> 2;
    const int t = lane & 3;
    // exp2-domain: fold log2e into the Q pre-scale; p = exp2(s')
    const float rs = 0.17677669529663687f * 1.4426950408889634f;

    const int r0l = warp * 16 + g;
    const int r1l = r0l + 8;
    const int* maskb = mask + b * L_;
    const int noMask = g_mflag[b];

    // ---- Q fragments: 2 k16-steps, split fp16 (22-bit Q) ----
    const float s0 = scale_w[h * L_ + q0 + r0l] * rs;
    const float s1 = scale_w[h * L_ + q0 + r1l] * rs;
    const float* qb = q + (size_t)(b * L_ + q0) * H_ + h * DH_;

    uint32_t qh2[2][4], ql2[2][4];
    #pragma unroll
    for (int s = 0; s < 2; s++) {
        float2 v0 = *(const float2*)&qb[r0l * H_ + s * 16 + 2 * t];
        float2 v2 = *(const float2*)&qb[r0l * H_ + s * 16 + 2 * t + 8];
        float2 v1 = *(const float2*)&qb[r1l * H_ + s * 16 + 2 * t];
        float2 v3 = *(const float2*)&qb[r1l * H_ + s * 16 + 2 * t + 8];
        split2h(v0.x * s0, v0.y * s0, qh2[s][0], ql2[s][0]);
        split2h(v1.x * s1, v1.y * s1, qh2[s][1], ql2[s][1]);
        split2h(v2.x * s0, v2.y * s0, qh2[s][2], ql2[s][2]);
        split2h(v3.x * s1, v3.y * s1, qh2[s][3], ql2[s][3]);
    }

    float l0 = 0.f, l1 = 0.f;
    float o[4][4] = {};

    const int koff = g * 16 + t * 4;
    const int voff = g * 36 + t * 8;

    fill_tile(sbase, 0, bh, 0, maskb);

    for (int kt = 0; kt < 16; kt++) {
        const int buf = (kt & 1) ? BUFSZ : 0;
        cp_wait0();
        __syncthreads();
        if (kt + 1 < 16)
            fill_tile(sbase, (kt & 1) ? 0 : BUFSZ, bh, kt + 1, maskb);

        #pragma unroll
        for (int sx = 0; sx < 2; sx++) {
            const uint32_t* KH = smu + buf + OKH + sx * 1024;
            const uint32_t* VH = smu + buf + OVH + sx * 1152;
            const uint32_t* VL = smu + buf + OVL + sx * 1152;
            const int*      MS = (const int*)(smu + buf + OMS) + sx * 64;

            // ======== S half0 ========
            float c0[4][4] = {};
            #pragma unroll
            for (int jj = 0; jj < 4; jj++) {
                uint4 bhw = *(const uint4*)(KH + jj * 128 + koff);
                mma16h(c0[jj], qh2[0], bhw.x, bhw.y);
                mma16h(c0[jj], qh2[1], bhw.z, bhw.w);
                mma16h(c0[jj], ql2[0], bhw.x, bhw.y);
                mma16h(c0[jj], ql2[1], bhw.z, bhw.w);
            }
            if (!noMask) {
                #pragma unroll
                for (int jj = 0; jj < 4; jj++) {
                    int2 mv = *(const int2*)(MS + jj * 8 + 2 * t);
                    if (mv.x == 0) { c0[jj][0] = -1e9f; c0[jj][2] = -1e9f; }
                    if (mv.y == 0) { c0[jj][1] = -1e9f; c0[jj][3] = -1e9f; }
                }
            }
            // ======== exp/pack half0 ========
            uint32_t APH0[2][4], APL0[2][4];
            #pragma unroll
            for (int kb2 = 0; kb2 < 2; kb2++) {
                float pA0 = ex2f(c0[2*kb2][0]);
                float pA1 = ex2f(c0[2*kb2][1]);
                float pA2 = ex2f(c0[2*kb2][2]);
                float pA3 = ex2f(c0[2*kb2][3]);
                float pB0 = ex2f(c0[2*kb2+1][0]);
                float pB1 = ex2f(c0[2*kb2+1][1]);
                float pB2 = ex2f(c0[2*kb2+1][2]);
                float pB3 = ex2f(c0[2*kb2+1][3]);
                l0 += pA0 + pA1 + pB0 + pB1;
                l1 += pA2 + pA3 + pB2 + pB3;
                split2(pA0, pA1, APH0[kb2][0], APL0[kb2][0]);
                split2(pA2, pA3, APH0[kb2][1], APL0[kb2][1]);
                split2(pB0, pB1, APH0[kb2][2], APL0[kb2][2]);
                split2(pB2, pB3, APH0[kb2][3], APL0[kb2][3]);
            }
            // ======== S half1 ========
            float c1[4][4] = {};
            #pragma unroll
            for (int jj = 0; jj < 4; jj++) {
                uint4 bhw = *(const uint4*)(KH + (jj + 4) * 128 + koff);
                mma16h(c1[jj], qh2[0], bhw.x, bhw.y);
                mma16h(c1[jj], qh2[1], bhw.z, bhw.w);
                mma16h(c1[jj], ql2[0], bhw.x, bhw.y);
                mma16h(c1[jj], ql2[1], bhw.z, bhw.w);
            }
            // ======== PV half0 ========
            #pragma unroll
            for (int nb = 0; nb < 4; nb++) {
                uint4 vh = *(const uint4*)(VH + nb * 288 + voff);
                uint4 vl = *(const uint4*)(VL + nb * 288 + voff);
                mma16(o[nb], APH0[0], vh.x, vh.y);
                mma16(o[nb], APH0[1], vh.z, vh.w);
                mma16(o[nb], APL0[0], vh.x, vh.y);
                mma16(o[nb], APL0[1], vh.z, vh.w);
                mma16(o[nb], APH0[0], vl.x, vl.y);
                mma16(o[nb], APH0[1], vl.z, vl.w);
            }
            // ======== mask + exp/pack half1 ========
            if (!noMask) {
                #pragma unroll
                for (int jj = 0; jj < 4; jj++) {
                    int2 mv = *(const int2*)(MS + (jj + 4) * 8 + 2 * t);
                    if (mv.x == 0) { c1[jj][0] = -1e9f; c1[jj][2] = -1e9f; }
                    if (mv.y == 0) { c1[jj][1] = -1e9f; c1[jj][3] = -1e9f; }
                }
            }
            uint32_t APH1[2][4], APL1[2][4];
            #pragma unroll
            for (int kb2 = 0; kb2 < 2; kb2++) {
                float pA0 = ex2f(c1[2*kb2][0]);
                float pA1 = ex2f(c1[2*kb2][1]);
                float pA2 = ex2f(c1[2*kb2][2]);
                float pA3 = ex2f(c1[2*kb2][3]);
                float pB0 = ex2f(c1[2*kb2+1][0]);
                float pB1 = ex2f(c1[2*kb2+1][1]);
                float pB2 = ex2f(c1[2*kb2+1][2]);
                float pB3 = ex2f(c1[2*kb2+1][3]);
                l0 += pA0 + pA1 + pB0 + pB1;
                l1 += pA2 + pA3 + pB2 + pB3;
                split2(pA0, pA1, APH1[kb2][0], APL1[kb2][0]);
                split2(pA2, pA3, APH1[kb2][1], APL1[kb2][1]);
                split2(pB0, pB1, APH1[kb2][2], APL1[kb2][2]);
                split2(pB2, pB3, APH1[kb2][3], APL1[kb2][3]);
            }
            // ======== PV half1 ========
            #pragma unroll
            for (int nb = 0; nb < 4; nb++) {
                uint4 vh = *(const uint4*)(VH + nb * 288 + voff + 4);
                uint4 vl = *(const uint4*)(VL + nb * 288 + voff + 4);
                mma16(o[nb], APH1[0], vh.x, vh.y);
                mma16(o[nb], APH1[1], vh.z, vh.w);
                mma16(o[nb], APL1[0], vh.x, vh.y);
                mma16(o[nb], APL1[1], vh.z, vh.w);
                mma16(o[nb], APH1[0], vl.x, vl.y);
                mma16(o[nb], APH1[1], vl.z, vl.w);
            }
        }
    }

    // ---- one-time l reduction across the 4-lane groups ----
    l0 += __shfl_xor_sync(0xffffffffu, l0, 1);
    l0 += __shfl_xor_sync(0xffffffffu, l0, 2);
    l1 += __shfl_xor_sync(0xffffffffu, l1, 1);
    l1 += __shfl_xor_sync(0xffffffffu, l1, 2);

    // ---- normalize + store (fused head transpose) ----
    float inv0 = 1.f / l0, inv1 = 1.f / l1;
    #pragma unroll
    for (int nb = 0; nb < 4; nb++) {
        int col = h * DH_ + nb * 8 + 2 * t;
        float2 w0 = make_float2(o[nb][0] * inv0, o[nb][1] * inv0);
        float2 w1 = make_float2(o[nb][2] * inv1, o[nb][3] * inv1);
        *(float2*)&g_hidden[(size_t)(b * L_ + q0 + r0l) * H_ + col] = w0;
        *(float2*)&g_hidden[(size_t)(b * L_ + q0 + r1l) * H_ + col] = w1;
    }
}

// ---------------------------------------------------------------------------
// Launch. Inputs: 0=q 1=k 2=v 3=k_b 4=mask 5=scale_w 6=Wb 7=bb 8=Ww 9=bw
// ---------------------------------------------------------------------------
extern "C" void kernel_launch(void* const* d_in, const int* in_sizes, int n_in,
                              void* d_out, int out_size)
{
    const float* q       = (const float*)d_in[0];
    const float* k       = (const float*)d_in[1];
    const float* v       = (const float*)d_in[2];
    const float* k_b     = (const float*)d_in[3];
    const int*   mask    = (const int*)  d_in[4];
    const float* scale_w = (const float*)d_in[5];
    const float* Wb      = (const float*)d_in[6];
    const float* bb      = (const float*)d_in[7];
    const float* Ww      = (const float*)d_in[8];
    const float* bw      = (const float*)d_in[9];
    float* out = (float*)d_out;

    cudaFuncSetAttribute(attn_tc, cudaFuncAttributeMaxDynamicSharedMemorySize,
                         ATTN_SMEM_BYTES);
    cudaFuncSetAttribute(gemm_keff,
                         cudaFuncAttributeMaxDynamicSharedMemorySize, GK_SMEM_BYTES);
    cudaFuncSetAttribute(gemm_out,
                         cudaFuncAttributeMaxDynamicSharedMemorySize, GEMM_SMEM_BYTES);

    // mask all-ones flags + V split/transpose prep
    maskflag<<<B_, 128>>>(mask);
    vprep<<<B_ * NH_ * 32, 128>>>(v);

    // keff = k_b @ Wb^T + bb + k   (written directly as fp16 K image)
    gemm_keff<<<dim3(H_ / 64, M_ / 128), 256, GK_SMEM_BYTES>>>(k_b, Wb, bb, k);

    // hidden = attention(q, keff, v)
    attn_tc<<<dim3(L_ / 128, NH_, B_), 256, ATTN_SMEM_BYTES>>>(q, mask, scale_w);

    // out = hidden @ Ww^T + bw
    gemm_out<<<dim3(H_ / 64, M_ / 128), 256, GEMM_SMEM_BYTES>>>(Ww, bw, out);
}

// round 16
// speedup vs baseline: 1.3398x; 1.0494x over previous
#include <cuda_runtime.h>
#include <cuda_fp16.h>
#include <cstdint>

#define B_  4
#define L_  2048
#define H_  256
#define NH_ 8
#define DH_ 32
#define M_  (B_*L_)   // 8192 rows

// ---------------------------------------------------------------------------
// Global scratch (allocation-free rule: __device__ globals)
// K(eff) fp16 words (single, unsplit), [b][h][tile64][key64][16 words]
// V^T split bf16 words, [b][h][tile64][drow32][36 words] (32 used)
// ---------------------------------------------------------------------------
__device__ __align__(16) uint32_t g_kh[B_*NH_*32*64*16];
__device__ __align__(16) uint32_t g_vh[B_*NH_*32*32*36];
__device__ __align__(16) uint32_t g_vl[B_*NH_*32*32*36];
__device__ __align__(16) float    g_hidden[M_ * H_];
__device__ int g_mflag[B_];   // 1 = no masked keys in this batch row

// ---------------------------------------------------------------------------
// helpers
// ---------------------------------------------------------------------------
__device__ __forceinline__ float ex2f(float x) {
    float r; asm("ex2.approx.f32 %0, %1;" : "=f"(r) : "f"(x)); return r;
}
// bf16 mma (attention PV)
__device__ __forceinline__ void mma16(float c[4], const uint32_t a[4],
                                      uint32_t b0, uint32_t b1) {
    asm("mma.sync.aligned.m16n8k16.row.col.f32.bf16.bf16.f32 "
        "{%0,%1,%2,%3},{%4,%5,%6,%7},{%8,%9},{%0,%1,%2,%3};"
        : "+f"(c[0]), "+f"(c[1]), "+f"(c[2]), "+f"(c[3])
        : "r"(a[0]), "r"(a[1]), "r"(a[2]), "r"(a[3]), "r"(b0), "r"(b1));
}
// fp16 mma (S + both GEMMs)
__device__ __forceinline__ void mma16h(float c[4], const uint32_t a[4],
                                       uint32_t b0, uint32_t b1) {
    asm("mma.sync.aligned.m16n8k16.row.col.f32.f16.f16.f32 "
        "{%0,%1,%2,%3},{%4,%5,%6,%7},{%8,%9},{%0,%1,%2,%3};"
        : "+f"(c[0]), "+f"(c[1]), "+f"(c[2]), "+f"(c[3])
        : "r"(a[0]), "r"(a[1]), "r"(a[2]), "r"(a[3]), "r"(b0), "r"(b1));
}
// bf16 pack/split
__device__ __forceinline__ uint32_t packbf(float x, float y) {
    uint32_t r; asm("cvt.rn.bf16x2.f32 %0, %1, %2;" : "=r"(r) : "f"(y), "f"(x));
    return r;
}
__device__ __forceinline__ void split2(float x, float y,
                                       uint32_t& hw, uint32_t& lw) {
    hw = packbf(x, y);
    float xh = __uint_as_float(hw << 16);
    float yh = __uint_as_float(hw & 0xffff0000u);
    lw = packbf(x - xh, y - yh);
}
// fp16 pack/split
__device__ __forceinline__ uint32_t packh(float x, float y) {
    uint32_t r; asm("cvt.rn.f16x2.f32 %0, %1, %2;" : "=r"(r) : "f"(y), "f"(x));
    return r;
}
__device__ __forceinline__ void split2h(float x, float y,
                                        uint32_t& hw, uint32_t& lw) {
    hw = packh(x, y);
    __half2 h2 = *reinterpret_cast<__half2*>(&hw);
    float xh = __half2float(__low2half(h2));
    float yh = __half2float(__high2half(h2));
    lw = packh(x - xh, y - yh);
}
__device__ __forceinline__ void cp16(uint32_t saddr, const void* gaddr) {
    asm volatile("cp.async.cg.shared.global [%0], [%1], 16;"
                 :: "r"(saddr), "l"(gaddr));
}
__device__ __forceinline__ void cp_commit() {
    asm volatile("cp.async.commit_group;");
}
__device__ __forceinline__ void cp_wait0() {
    asm volatile("cp.async.wait_group 0;" ::: "memory");
}

// word-position permutations: u = w&7, s = w>>3
// K rows have 16 words: pos = (u&3)*4 + 2s + (u>>2)
// V rows have 32 words: pos = (u&3)*8 + 2s + (u>>2)
__device__ __forceinline__ int kpos(int w) {
    return ((w & 3) << 2) + ((w >> 3) << 1) + ((w >> 2) & 1);
}
__device__ __forceinline__ int vpos(int w) {
    return ((w & 3) << 3) + ((w >> 3) << 1) + ((w >> 2) & 1);
}

// ---------------------------------------------------------------------------
// Shared GEMM smem layout (fp16 2x: A hi | A lo | W), double-buffered
// ---------------------------------------------------------------------------
#define KAH 0
#define KAL (128 * 20)
#define KWH (2 * 128 * 20)
#define KBUF (2 * 128 * 20 + 64 * 20)      // 6400 words per buffer
#define GK_SMEM_WORDS (2 * KBUF)
#define GK_SMEM_BYTES (GK_SMEM_WORDS * 4)  // 51200 B

// fp16 2x GEMM core: acc += A(split fp16) @ W(single fp16)^T over K=256.
// Caller provides smem base and out-of-loop prefetch; body identical for
// keff and output GEMMs.
template<typename EPI>
__device__ __forceinline__ void gemm_f16_core(
    uint32_t* __restrict__ smw,
    const float* __restrict__ A, const float* __restrict__ W,
    int m0, int n0, EPI epilogue)
{
    const int tid = threadIdx.x;
    const int warp   = tid >> 5;
    const int lane   = tid & 31;
    const int warp_m = warp >> 1;
    const int warp_n = warp & 1;
    const int g = lane >> 2;
    const int t = lane & 3;

    float acc[2][4][4] = {};

    float4 xa[4], xw[2];
    #pragma unroll
    for (int u = 0; u < 4; u++) {
        int idx = tid + u * 256;
        xa[u] = *(const float4*)&A[(size_t)(m0 + (idx >> 3)) * H_ + (idx & 7) * 4];
    }
    #pragma unroll
    for (int u = 0; u < 2; u++) {
        int idx = tid + u * 256;
        xw[u] = *(const float4*)&W[(size_t)(n0 + (idx >> 3)) * H_ + (idx & 7) * 4];
    }

    for (int k0 = 0; k0 < H_; k0 += 32) {
        const int bb = ((k0 >> 5) & 1) ? KBUF : 0;
        #pragma unroll
        for (int u = 0; u < 4; u++) {
            int idx = tid + u * 256;
            int row = idx >> 3, c4 = idx & 7;
            uint32_t h0, l0, h1, l1;
            split2h(xa[u].x, xa[u].y, h0, l0);
            split2h(xa[u].z, xa[u].w, h1, l1);
            *(uint2*)&smw[bb + KAH + row * 20 + c4 * 2] = make_uint2(h0, h1);
            *(uint2*)&smw[bb + KAL + row * 20 + c4 * 2] = make_uint2(l0, l1);
        }
        #pragma unroll
        for (int u = 0; u < 2; u++) {
            int idx = tid + u * 256;
            int row = idx >> 3, c4 = idx & 7;
            uint32_t h0 = packh(xw[u].x, xw[u].y);
            uint32_t h1 = packh(xw[u].z, xw[u].w);
            *(uint2*)&smw[bb + KWH + row * 20 + c4 * 2] = make_uint2(h0, h1);
        }
        __syncthreads();

        if (k0 + 32 < H_) {
            #pragma unroll
            for (int u = 0; u < 4; u++) {
                int idx = tid + u * 256;
                xa[u] = *(const float4*)&A[(size_t)(m0 + (idx >> 3)) * H_ +
                                           k0 + 32 + (idx & 7) * 4];
            }
            #pragma unroll
            for (int u = 0; u < 2; u++) {
                int idx = tid + u * 256;
                xw[u] = *(const float4*)&W[(size_t)(n0 + (idx >> 3)) * H_ +
                                           k0 + 32 + (idx & 7) * 4];
            }
        }

        #pragma unroll
        for (int s = 0; s < 2; s++) {
            uint32_t ah[2][4], al[2][4];
            #pragma unroll
            for (int mt = 0; mt < 2; mt++) {
                int r0 = bb + (warp_m * 32 + mt * 16 + g) * 20 + 8 * s + t;
                ah[mt][0] = smw[KAH + r0];
                ah[mt][1] = smw[KAH + r0 + 160];
                ah[mt][2] = smw[KAH + r0 + 4];
                ah[mt][3] = smw[KAH + r0 + 164];
                al[mt][0] = smw[KAL + r0];
                al[mt][1] = smw[KAL + r0 + 160];
                al[mt][2] = smw[KAL + r0 + 4];
                al[mt][3] = smw[KAL + r0 + 164];
            }
            #pragma unroll
            for (int nt = 0; nt < 4; nt++) {
                int rw = bb + (warp_n * 32 + nt * 8 + g) * 20 + 8 * s + t;
                uint32_t wh0 = smw[KWH + rw];
                uint32_t wh1 = smw[KWH + rw + 4];
                #pragma unroll
                for (int mt = 0; mt < 2; mt++) {
                    mma16h(acc[mt][nt], al[mt], wh0, wh1);
                    mma16h(acc[mt][nt], ah[mt], wh0, wh1);
                }
            }
        }
        // no trailing sync: double-buffered; reuse gated by next iter's sync
    }

    #pragma unroll
    for (int mt = 0; mt < 2; mt++)
        #pragma unroll
        for (int nt = 0; nt < 4; nt++) {
            int n  = n0 + warp_n * 32 + nt * 8 + 2 * t;
            int mA = m0 + warp_m * 32 + mt * 16 + g;
            epilogue(acc[mt][nt], mA, n);
        }
}

// ---------------------------------------------------------------------------
// Fused prep + keff kernel. grid = 512 x 256 threads:
//  blocks 0..255  : keff GEMM (fp16 2x), writes fp16 K image
//  blocks 256..511: V prep (4 tiles each) + mask flags (first 4 blocks)
// ---------------------------------------------------------------------------
__global__ __launch_bounds__(256)
void prep_keff(const float* __restrict__ k_b,
               const float* __restrict__ Wb,
               const float* __restrict__ bb,
               const float* __restrict__ kadd,
               const float* __restrict__ v,
               const int*   __restrict__ mask)
{
    extern __shared__ uint32_t smw[];
    const int bx  = blockIdx.x;
    const int tid = threadIdx.x;

    if (bx < 256) {
        const int m0 = (bx >> 2) * 128;
        const int n0 = (bx & 3) * 64;
        gemm_f16_core(smw, k_b, Wb, m0, n0,
            [&](float a[4], int mA, int n) {
                int mB = mA + 8;
                float2 bs = *(const float2*)&bb[n];
                float x0 = a[0] + bs.x, x1 = a[1] + bs.y;
                float y0 = a[2] + bs.x, y1 = a[3] + bs.y;
                float2 a0 = *(const float2*)&kadd[(size_t)mA * H_ + n];
                float2 a1 = *(const float2*)&kadd[(size_t)mB * H_ + n];
                x0 += a0.x; x1 += a0.y; y0 += a1.x; y1 += a1.y;
                int h = n >> 5;
                int wd = (n & 31) >> 1;
                int p = kpos(wd);
                {
                    int bi = mA >> 11, l = mA & 2047;
                    size_t base = (((size_t)(bi * NH_ + h) * 32 + (l >> 6)) * 64
                                   + (l & 63)) * 16 + p;
                    g_kh[base] = packh(x0, x1);
                }
                {
                    int bi = mB >> 11, l = mB & 2047;
                    size_t base = (((size_t)(bi * NH_ + h) * 32 + (l >> 6)) * 64
                                   + (l & 63)) * 16 + p;
                    g_kh[base] = packh(y0, y1);
                }
            });
        return;
    }

    // ---- V prep: 4 tiles per block, 256 threads ----
    const int vb = bx - 256;            // 0..255
    float*    sv  = (float*)smw;        // 2304 words
    uint32_t* swh = smw + 2304;         // 1152
    uint32_t* swl = smw + 3456;         // 1152

    for (int tt = 0; tt < 4; tt++) {
        int tile = vb * 4 + tt;         // 0..1023
        int kt = tile & 31, h = (tile >> 5) & 7, b = tile >> 8;
        const float* src = v + ((size_t)(b * L_ + kt * 64)) * H_ + h * 32;
        __syncthreads();                // sv/swh/swl reuse across tiles
        #pragma unroll
        for (int u = 0; u < 2; u++) {
            int idx = tid + u * 256;
            int row = idx >> 3, c4 = idx & 7;
            *(float4*)&sv[row * 36 + c4 * 4] =
                *(const float4*)&src[row * H_ + c4 * 4];
        }
        __syncthreads();
        #pragma unroll
        for (int u = 0; u < 4; u++) {
            int idx = tid + u * 256;
            int drow = idx >> 5, w = idx & 31;
            float x = sv[(2 * w) * 36 + drow];
            float y = sv[(2 * w + 1) * 36 + drow];
            uint32_t hw, lw; split2(x, y, hw, lw);
            int p = vpos(w);
            swh[drow * 36 + p] = hw;
            swl[drow * 36 + p] = lw;
        }
        __syncthreads();
        uint32_t* gh = g_vh + (size_t)tile * 1152;
        uint32_t* gl = g_vl + (size_t)tile * 1152;
        #pragma unroll
        for (int u = 0; u < 5; u++) {
            int idx = tid + u * 256;
            if (idx < 1152) { gh[idx] = swh[idx]; gl[idx] = swl[idx]; }
        }
    }

    // ---- mask flags (blocks 256..259 only) ----
    if (vb < 4) {
        int b = vb;
        int all1 = 1;
        for (int i = tid; i < L_; i += 256) all1 &= (mask[b * L_ + i] != 0);
        __syncthreads();
        int* s = (int*)smw;
        s[tid] = all1;
        __syncthreads();
        for (int st = 128; st; st >>= 1) {
            if (tid < st) s[tid] &= s[tid + st];
            __syncthreads();
        }
        if (tid == 0) g_mflag[b] = s[0];
    }
}

// ---------------------------------------------------------------------------
// Output GEMM (fp16 2x): out = hidden @ Ww^T + bw
// ---------------------------------------------------------------------------
__global__ __launch_bounds__(256)
void gemm_out(const float* __restrict__ W,
              const float* __restrict__ bias,
              float* __restrict__ outp)
{
    extern __shared__ uint32_t smw[];
    const int m0 = blockIdx.y * 128;
    const int n0 = blockIdx.x * 64;
    gemm_f16_core(smw, g_hidden, W, m0, n0,
        [&](float a[4], int mA, int n) {
            int mB = mA + 8;
            float2 bs = *(const float2*)&bias[n];
            *(float2*)&outp[(size_t)mA * H_ + n] =
                make_float2(a[0] + bs.x, a[1] + bs.y);
            *(float2*)&outp[(size_t)mB * H_ + n] =
                make_float2(a[2] + bs.x, a[3] + bs.y);
        });
}

// ---------------------------------------------------------------------------
// Flash attention (UNCHANGED from R14 winner): S fp16 (Q split, K single),
// PV bf16x3, static exp2 softmax, P in registers, BK=128 double-buffered.
// smem words/buffer: KH 2048 | VH 2304 | VL 2304 | MS 128 = 6784.
// ---------------------------------------------------------------------------
#define OKH 0
#define OVH 2048
#define OVL 4352
#define OMS 6656
#define BUFSZ 6784
#define ATTN_SMEM_WORDS (2 * BUFSZ)
#define ATTN_SMEM_BYTES (ATTN_SMEM_WORDS * 4)

__device__ __forceinline__ void fill_tile(uint32_t sbase, int bufbase,
                                          int bh, int kt,
                                          const int* __restrict__ maskb)
{
    const int tid = threadIdx.x;
    const uint32_t* gkh = g_kh + (size_t)bh * 32768 + (size_t)kt * 2048;
    const uint32_t* gvh = g_vh + (size_t)bh * 36864 + (size_t)kt * 2304;
    const uint32_t* gvl = g_vl + (size_t)bh * 36864 + (size_t)kt * 2304;
    #pragma unroll
    for (int u = 0; u < 2; u++) {
        int i = (tid + u * 256) * 4;
        cp16(sbase + (bufbase + OKH) * 4 + i * 4, gkh + i);
    }
    #pragma unroll
    for (int u = 0; u < 3; u++) {
        int i = tid + u * 256;
        if (i < 576) {
            cp16(sbase + (bufbase + OVH + i * 4) * 4, gvh + i * 4);
            cp16(sbase + (bufbase + OVL + i * 4) * 4, gvl + i * 4);
        }
    }
    if (tid < 32)
        cp16(sbase + (bufbase + OMS + tid * 4) * 4, maskb + kt * 128 + tid * 4);
    cp_commit();
}

__global__ __launch_bounds__(256)
void attn_tc(const float* __restrict__ q,
             const int*   __restrict__ mask,
             const float* __restrict__ scale_w)
{
    extern __shared__ uint32_t smu[];
    const uint32_t sbase = (uint32_t)__cvta_generic_to_shared(smu);

    const int b   = blockIdx.z;
    const int h   = blockIdx.y;
    const int q0  = blockIdx.x * 128;
    const int bh  = b * NH_ + h;
    const int tid = threadIdx.x;
    const int warp = tid >> 5;
    const int lane = tid & 31;
    const int g = lane >> 2;
    const int t = lane & 3;
    const float rs = 0.17677669529663687f * 1.4426950408889634f;

    const int r0l = warp * 16 + g;
    const int r1l = r0l + 8;
    const int* maskb = mask + b * L_;
    const int noMask = g_mflag[b];

    const float s0 = scale_w[h * L_ + q0 + r0l] * rs;
    const float s1 = scale_w[h * L_ + q0 + r1l] * rs;
    const float* qb = q + (size_t)(b * L_ + q0) * H_ + h * DH_;

    uint32_t qh2[2][4], ql2[2][4];
    #pragma unroll
    for (int s = 0; s < 2; s++) {
        float2 v0 = *(const float2*)&qb[r0l * H_ + s * 16 + 2 * t];
        float2 v2 = *(const float2*)&qb[r0l * H_ + s * 16 + 2 * t + 8];
        float2 v1 = *(const float2*)&qb[r1l * H_ + s * 16 + 2 * t];
        float2 v3 = *(const float2*)&qb[r1l * H_ + s * 16 + 2 * t + 8];
        split2h(v0.x * s0, v0.y * s0, qh2[s][0], ql2[s][0]);
        split2h(v1.x * s1, v1.y * s1, qh2[s][1], ql2[s][1]);
        split2h(v2.x * s0, v2.y * s0, qh2[s][2], ql2[s][2]);
        split2h(v3.x * s1, v3.y * s1, qh2[s][3], ql2[s][3]);
    }

    float l0 = 0.f, l1 = 0.f;
    float o[4][4] = {};

    const int koff = g * 16 + t * 4;
    const int voff = g * 36 + t * 8;

    fill_tile(sbase, 0, bh, 0, maskb);

    for (int kt = 0; kt < 16; kt++) {
        const int buf = (kt & 1) ? BUFSZ : 0;
        cp_wait0();
        __syncthreads();
        if (kt + 1 < 16)
            fill_tile(sbase, (kt & 1) ? 0 : BUFSZ, bh, kt + 1, maskb);

        #pragma unroll
        for (int sx = 0; sx < 2; sx++) {
            const uint32_t* KH = smu + buf + OKH + sx * 1024;
            const uint32_t* VH = smu + buf + OVH + sx * 1152;
            const uint32_t* VL = smu + buf + OVL + sx * 1152;
            const int*      MS = (const int*)(smu + buf + OMS) + sx * 64;

            float c0[4][4] = {};
            #pragma unroll
            for (int jj = 0; jj < 4; jj++) {
                uint4 bhw = *(const uint4*)(KH + jj * 128 + koff);
                mma16h(c0[jj], qh2[0], bhw.x, bhw.y);
                mma16h(c0[jj], qh2[1], bhw.z, bhw.w);
                mma16h(c0[jj], ql2[0], bhw.x, bhw.y);
                mma16h(c0[jj], ql2[1], bhw.z, bhw.w);
            }
            if (!noMask) {
                #pragma unroll
                for (int jj = 0; jj < 4; jj++) {
                    int2 mv = *(const int2*)(MS + jj * 8 + 2 * t);
                    if (mv.x == 0) { c0[jj][0] = -1e9f; c0[jj][2] = -1e9f; }
                    if (mv.y == 0) { c0[jj][1] = -1e9f; c0[jj][3] = -1e9f; }
                }
            }
            uint32_t APH0[2][4], APL0[2][4];
            #pragma unroll
            for (int kb2 = 0; kb2 < 2; kb2++) {
                float pA0 = ex2f(c0[2*kb2][0]);
                float pA1 = ex2f(c0[2*kb2][1]);
                float pA2 = ex2f(c0[2*kb2][2]);
                float pA3 = ex2f(c0[2*kb2][3]);
                float pB0 = ex2f(c0[2*kb2+1][0]);
                float pB1 = ex2f(c0[2*kb2+1][1]);
                float pB2 = ex2f(c0[2*kb2+1][2]);
                float pB3 = ex2f(c0[2*kb2+1][3]);
                l0 += pA0 + pA1 + pB0 + pB1;
                l1 += pA2 + pA3 + pB2 + pB3;
                split2(pA0, pA1, APH0[kb2][0], APL0[kb2][0]);
                split2(pA2, pA3, APH0[kb2][1], APL0[kb2][1]);
                split2(pB0, pB1, APH0[kb2][2], APL0[kb2][2]);
                split2(pB2, pB3, APH0[kb2][3], APL0[kb2][3]);
            }
            float c1[4][4] = {};
            #pragma unroll
            for (int jj = 0; jj < 4; jj++) {
                uint4 bhw = *(const uint4*)(KH + (jj + 4) * 128 + koff);
                mma16h(c1[jj], qh2[0], bhw.x, bhw.y);
                mma16h(c1[jj], qh2[1], bhw.z, bhw.w);
                mma16h(c1[jj], ql2[0], bhw.x, bhw.y);
                mma16h(c1[jj], ql2[1], bhw.z, bhw.w);
            }
            #pragma unroll
            for (int nb = 0; nb < 4; nb++) {
                uint4 vh = *(const uint4*)(VH + nb * 288 + voff);
                uint4 vl = *(const uint4*)(VL + nb * 288 + voff);
                mma16(o[nb], APH0[0], vh.x, vh.y);
                mma16(o[nb], APH0[1], vh.z, vh.w);
                mma16(o[nb], APL0[0], vh.x, vh.y);
                mma16(o[nb], APL0[1], vh.z, vh.w);
                mma16(o[nb], APH0[0], vl.x, vl.y);
                mma16(o[nb], APH0[1], vl.z, vl.w);
            }
            if (!noMask) {
                #pragma unroll
                for (int jj = 0; jj < 4; jj++) {
                    int2 mv = *(const int2*)(MS + (jj + 4) * 8 + 2 * t);
                    if (mv.x == 0) { c1[jj][0] = -1e9f; c1[jj][2] = -1e9f; }
                    if (mv.y == 0) { c1[jj][1] = -1e9f; c1[jj][3] = -1e9f; }
                }
            }
            uint32_t APH1[2][4], APL1[2][4];
            #pragma unroll
            for (int kb2 = 0; kb2 < 2; kb2++) {
                float pA0 = ex2f(c1[2*kb2][0]);
                float pA1 = ex2f(c1[2*kb2][1]);
                float pA2 = ex2f(c1[2*kb2][2]);
                float pA3 = ex2f(c1[2*kb2][3]);
                float pB0 = ex2f(c1[2*kb2+1][0]);
                float pB1 = ex2f(c1[2*kb2+1][1]);
                float pB2 = ex2f(c1[2*kb2+1][2]);
                float pB3 = ex2f(c1[2*kb2+1][3]);
                l0 += pA0 + pA1 + pB0 + pB1;
                l1 += pA2 + pA3 + pB2 + pB3;
                split2(pA0, pA1, APH1[kb2][0], APL1[kb2][0]);
                split2(pA2, pA3, APH1[kb2][1], APL1[kb2][1]);
                split2(pB0, pB1, APH1[kb2][2], APL1[kb2][2]);
                split2(pB2, pB3, APH1[kb2][3], APL1[kb2][3]);
            }
            #pragma unroll
            for (int nb = 0; nb < 4; nb++) {
                uint4 vh = *(const uint4*)(VH + nb * 288 + voff + 4);
                uint4 vl = *(const uint4*)(VL + nb * 288 + voff + 4);
                mma16(o[nb], APH1[0], vh.x, vh.y);
                mma16(o[nb], APH1[1], vh.z, vh.w);
                mma16(o[nb], APL1[0], vh.x, vh.y);
                mma16(o[nb], APL1[1], vh.z, vh.w);
                mma16(o[nb], APH1[0], vl.x, vl.y);
                mma16(o[nb], APH1[1], vl.z, vl.w);
            }
        }
    }

    l0 += __shfl_xor_sync(0xffffffffu, l0, 1);
    l0 += __shfl_xor_sync(0xffffffffu, l0, 2);
    l1 += __shfl_xor_sync(0xffffffffu, l1, 1);
    l1 += __shfl_xor_sync(0xffffffffu, l1, 2);

    float inv0 = 1.f / l0, inv1 = 1.f / l1;
    #pragma unroll
    for (int nb = 0; nb < 4; nb++) {
        int col = h * DH_ + nb * 8 + 2 * t;
        float2 w0 = make_float2(o[nb][0] * inv0, o[nb][1] * inv0);
        float2 w1 = make_float2(o[nb][2] * inv1, o[nb][3] * inv1);
        *(float2*)&g_hidden[(size_t)(b * L_ + q0 + r0l) * H_ + col] = w0;
        *(float2*)&g_hidden[(size_t)(b * L_ + q0 + r1l) * H_ + col] = w1;
    }
}

// ---------------------------------------------------------------------------
// Launch. Inputs: 0=q 1=k 2=v 3=k_b 4=mask 5=scale_w 6=Wb 7=bb 8=Ww 9=bw
// ---------------------------------------------------------------------------
extern "C" void kernel_launch(void* const* d_in, const int* in_sizes, int n_in,
                              void* d_out, int out_size)
{
    const float* q       = (const float*)d_in[0];
    const float* k       = (const float*)d_in[1];
    const float* v       = (const float*)d_in[2];
    const float* k_b     = (const float*)d_in[3];
    const int*   mask    = (const int*)  d_in[4];
    const float* scale_w = (const float*)d_in[5];
    const float* Wb      = (const float*)d_in[6];
    const float* bb      = (const float*)d_in[7];
    const float* Ww      = (const float*)d_in[8];
    const float* bw      = (const float*)d_in[9];
    float* out = (float*)d_out;

    cudaFuncSetAttribute(attn_tc, cudaFuncAttributeMaxDynamicSharedMemorySize,
                         ATTN_SMEM_BYTES);
    cudaFuncSetAttribute(prep_keff,
                         cudaFuncAttributeMaxDynamicSharedMemorySize, GK_SMEM_BYTES);
    cudaFuncSetAttribute(gemm_out,
                         cudaFuncAttributeMaxDynamicSharedMemorySize, GK_SMEM_BYTES);

    // fused: keff GEMM (fp16 K image) + V prep + mask flags
    prep_keff<<<512, 256, GK_SMEM_BYTES>>>(k_b, Wb, bb, k, v, mask);

    // hidden = attention(q, keff, v)
    attn_tc<<<dim3(L_ / 128, NH_, B_), 256, ATTN_SMEM_BYTES>>>(q, mask, scale_w);

    // out = hidden @ Ww^T + bw   (fp16 2x)
    gemm_out<<<dim3(H_ / 64, M_ / 128), 256, GK_SMEM_BYTES>>>(Ww, bw, out);
}